// round 2
// baseline (speedup 1.0000x reference)
#include <cuda_runtime.h>
#include <math.h>

// ---------------------------------------------------------------------------
// GPT transformer block, fp32 baseline.
//   B=2, T=2048, C=1024, H=16, HD=64
// Output layout (float32): [ x (B*T*C) | att_entropy (1) | present (2*B*H*T*HD) ]
// NOTE: present region starts at float offset XS+1 -> NOT 16B aligned.
//       Only scalar (4B) accesses are allowed on present; vectorized flash
//       reads go through aligned g_k/g_v scratch instead.
// ---------------------------------------------------------------------------

namespace {
constexpr int Bc = 2, Tc = 2048, Cc = 1024, Hc = 16, HDc = 64;
constexpr int Mrows = Bc * Tc;            // 4096
constexpr int XS    = Bc * Tc * Cc;       // 4194304
constexpr int PRES  = Bc * Hc * Tc * HDc; // 4194304
constexpr int FS    = 68;                 // flash smem row stride (pad)
constexpr int FLASH_SMEM = (4 * 64 * FS + 256) * 4; // 70656 B
}

// scratch (device globals -- no allocations allowed)
__device__ float g_h[Mrows * Cc];       // LN outputs / attention y (reused)
__device__ float g_q[PRES];             // Q in (B,H,T,HD)
__device__ float g_k[PRES];             // K in (B,H,T,HD)  (aligned copy)
__device__ float g_v[PRES];             // V in (B,H,T,HD)  (aligned copy)
__device__ float g_a[Mrows * 4 * Cc];   // FC activation (B,T,4C)

// ---------------------------------------------------------------------------
__global__ void zero_ent_kernel(float* e) { *e = 0.0f; }

// ---------------------------------------------------------------------------
// LayerNorm: one block per row, C=1024, 256 threads
__global__ void ln_kernel(const float* __restrict__ x,
                          const float* __restrict__ w,
                          const float* __restrict__ b,
                          float* __restrict__ out)
{
    int row = blockIdx.x;
    const float* xr = x + (long)row * Cc;
    float s = 0.f, s2 = 0.f;
    for (int i = threadIdx.x; i < Cc; i += 256) {
        float v = xr[i];
        s += v; s2 += v * v;
    }
    __shared__ float rs[32], rs2[32];
    #pragma unroll
    for (int o = 16; o; o >>= 1) {
        s  += __shfl_xor_sync(0xffffffffu, s,  o);
        s2 += __shfl_xor_sync(0xffffffffu, s2, o);
    }
    int lane = threadIdx.x & 31, wid = threadIdx.x >> 5;
    if (lane == 0) { rs[wid] = s; rs2[wid] = s2; }
    __syncthreads();
    if (wid == 0) {
        s  = (lane < 8) ? rs[lane]  : 0.f;
        s2 = (lane < 8) ? rs2[lane] : 0.f;
        #pragma unroll
        for (int o = 4; o; o >>= 1) {
            s  += __shfl_xor_sync(0xffffffffu, s,  o);
            s2 += __shfl_xor_sync(0xffffffffu, s2, o);
        }
        if (lane == 0) { rs[0] = s; rs2[0] = s2; }
    }
    __syncthreads();
    float mean = rs[0] * (1.0f / Cc);
    float var  = rs2[0] * (1.0f / Cc) - mean * mean;
    float inv  = rsqrtf(var + 1e-5f);
    float* o = out + (long)row * Cc;
    for (int i = threadIdx.x; i < Cc; i += 256)
        o[i] = (xr[i] - mean) * inv * w[i] + b[i];
}

// ---------------------------------------------------------------------------
__device__ __forceinline__ float gelu_f(float v) {
    const float c = 0.7978845608028654f;
    float u = c * (v + 0.044715f * v * v * v);
    return 0.5f * v * (1.0f + tanhf(u));
}

// ---------------------------------------------------------------------------
// SGEMM: C[M,N] = A[M,K] @ W[N,K]^T (+bias, +epilogue)
// BM=BN=128, BK=8, 256 threads, 8x8 per thread.
// EPI: 0 = QKV scatter (q->g_q; k->g_k+present; v->g_v+present, (B,H,T,HD))
//      1 = out = acc + bias + res   (residual add)
//      2 = out = gelu(acc + bias)
template <int EPI>
__global__ void gemm_kernel(const float* __restrict__ A,
                            const float* __restrict__ W,
                            const float* __restrict__ bias,
                            const float* __restrict__ res,
                            float* __restrict__ outp,
                            float* __restrict__ out_k,
                            float* __restrict__ out_v,
                            float* __restrict__ pres_k,
                            float* __restrict__ pres_v,
                            int K, int N)
{
    __shared__ float As[8][128];
    __shared__ float Bs[8][128];

    int tid = threadIdx.x;
    int mbase = blockIdx.y * 128, nbase = blockIdx.x * 128;
    int ty = tid >> 4, tx = tid & 15;
    int row0 = ty * 8, col0 = tx * 8;

    float acc[8][8] = {};

    int lm = tid >> 1;           // 0..127
    int lk = (tid & 1) * 4;      // 0 or 4
    const float* Ab = A + (long)(mbase + lm) * K + lk;
    const float* Wb = W + (long)(nbase + lm) * K + lk;

    for (int k0 = 0; k0 < K; k0 += 8) {
        float4 av = *(const float4*)(Ab + k0);
        float4 wv = *(const float4*)(Wb + k0);
        As[lk + 0][lm] = av.x; As[lk + 1][lm] = av.y;
        As[lk + 2][lm] = av.z; As[lk + 3][lm] = av.w;
        Bs[lk + 0][lm] = wv.x; Bs[lk + 1][lm] = wv.y;
        Bs[lk + 2][lm] = wv.z; Bs[lk + 3][lm] = wv.w;
        __syncthreads();
        #pragma unroll
        for (int k = 0; k < 8; k++) {
            float4 a0 = *(const float4*)&As[k][row0];
            float4 a1 = *(const float4*)&As[k][row0 + 4];
            float4 b0 = *(const float4*)&Bs[k][col0];
            float4 b1 = *(const float4*)&Bs[k][col0 + 4];
            float a[8] = {a0.x, a0.y, a0.z, a0.w, a1.x, a1.y, a1.z, a1.w};
            float bb[8] = {b0.x, b0.y, b0.z, b0.w, b1.x, b1.y, b1.z, b1.w};
            #pragma unroll
            for (int i = 0; i < 8; i++)
                #pragma unroll
                for (int j = 0; j < 8; j++)
                    acc[i][j] += a[i] * bb[j];
        }
        __syncthreads();
    }

    if (EPI == 0) {
        // QKV scatter; whole 128-wide tile lies in one of {q,k,v} regions
        int region = nbase >> 10;  // 0=q, 1=k, 2=v
        float* dst  = (region == 0) ? outp : (region == 1) ? out_k  : out_v;
        float* dst2 = (region == 0) ? nullptr
                    : (region == 1) ? pres_k : pres_v;
        #pragma unroll
        for (int i = 0; i < 8; i++) {
            int row = mbase + row0 + i;
            int bidx = row >> 11;        // row / T
            int t    = row & (Tc - 1);
            #pragma unroll
            for (int j = 0; j < 8; j++) {
                int n = nbase + col0 + j;
                float v = acc[i][j] + bias[n];
                int nl = n & (Cc - 1);
                int head = nl >> 6, d = nl & 63;
                long idx = (((long)(bidx * Hc + head) * Tc) + t) * HDc + d;
                dst[idx] = v;                      // aligned scratch (vector reads later)
                if (dst2) dst2[idx] = v;           // present output (scalar, 4B-aligned)
            }
        }
    } else {
        #pragma unroll
        for (int i = 0; i < 8; i++) {
            int row = mbase + row0 + i;
            #pragma unroll
            for (int j = 0; j < 8; j++) {
                int n = nbase + col0 + j;
                float v = acc[i][j] + bias[n];
                long idx = (long)row * N + n;
                if (EPI == 1) v += res[idx];
                if (EPI == 2) v = gelu_f(v);
                outp[idx] = v;
            }
        }
    }
}

// ---------------------------------------------------------------------------
// Flash attention with causal mask + entropy.
// Block: one (b, h, q-tile of 64). 256 threads (16x16, 4x4 S/O per thread).
// Q pre-scaled by 1/sqrt(HD). Entropy H = m + log(l) - ss/l per row.
__global__ void flash_kernel(const float* __restrict__ Q,
                             const float* __restrict__ Kp,
                             const float* __restrict__ Vp,
                             float* __restrict__ Y,
                             float* __restrict__ ent)
{
    extern __shared__ float sm[];
    float* Qs   = sm;                 // [64][FS]  (r, k-dim)
    float* KsT  = Qs  + 64 * FS;      // [64][FS]  (k-dim, key)  -- transposed
    float* Vs   = KsT + 64 * FS;      // [64][FS]  (key, d)
    float* Ps   = Vs  + 64 * FS;      // [64][FS]  (r, key)
    float* sm_m  = Ps + 64 * FS;
    float* sm_l  = sm_m + 64;
    float* sm_ss = sm_l + 64;
    float* sm_sc = sm_ss + 64;

    int qt = blockIdx.x, h = blockIdx.y, b = blockIdx.z;
    int tid = threadIdx.x;
    long bh = (long)(b * Hc + h);
    const float* Qg = Q  + (bh * Tc + qt * 64) * HDc;
    const float* Kg = Kp + bh * Tc * HDc;
    const float* Vg = Vp + bh * Tc * HDc;

    // load Q tile, scaled by 1/sqrt(64)
    for (int i = tid; i < 64 * 16; i += 256) {
        int r = i >> 4, d4 = (i & 15) * 4;
        float4 v = *(const float4*)(Qg + r * 64 + d4);
        Qs[r * FS + d4 + 0] = v.x * 0.125f;
        Qs[r * FS + d4 + 1] = v.y * 0.125f;
        Qs[r * FS + d4 + 2] = v.z * 0.125f;
        Qs[r * FS + d4 + 3] = v.w * 0.125f;
    }
    if (tid < 64) { sm_m[tid] = -1e30f; sm_l[tid] = 0.f; sm_ss[tid] = 0.f; }

    int ty = tid >> 4, tx = tid & 15;
    int r0 = ty * 4, c0 = tx * 4;
    float O[4][4] = {};
    __syncthreads();

    for (int kt = 0; kt <= qt; kt++) {
        // load K (transposed) and V tiles
        for (int i = tid; i < 64 * 16; i += 256) {
            int c = i >> 4, d4 = (i & 15) * 4;
            float4 kv = *(const float4*)(Kg + (kt * 64 + c) * 64 + d4);
            KsT[(d4 + 0) * FS + c] = kv.x;
            KsT[(d4 + 1) * FS + c] = kv.y;
            KsT[(d4 + 2) * FS + c] = kv.z;
            KsT[(d4 + 3) * FS + c] = kv.w;
            float4 vv = *(const float4*)(Vg + (kt * 64 + c) * 64 + d4);
            *(float4*)&Vs[c * FS + d4] = vv;
        }
        __syncthreads();

        // S = Qs @ K^T, 4x4 per thread
        float S[4][4] = {};
        #pragma unroll 4
        for (int k = 0; k < 64; k++) {
            float a0 = Qs[(r0 + 0) * FS + k];
            float a1 = Qs[(r0 + 1) * FS + k];
            float a2 = Qs[(r0 + 2) * FS + k];
            float a3 = Qs[(r0 + 3) * FS + k];
            float4 bv = *(const float4*)&KsT[k * FS + c0];
            S[0][0] += a0 * bv.x; S[0][1] += a0 * bv.y; S[0][2] += a0 * bv.z; S[0][3] += a0 * bv.w;
            S[1][0] += a1 * bv.x; S[1][1] += a1 * bv.y; S[1][2] += a1 * bv.z; S[1][3] += a1 * bv.w;
            S[2][0] += a2 * bv.x; S[2][1] += a2 * bv.y; S[2][2] += a2 * bv.z; S[2][3] += a2 * bv.w;
            S[3][0] += a3 * bv.x; S[3][1] += a3 * bv.y; S[3][2] += a3 * bv.z; S[3][3] += a3 * bv.w;
        }
        // causal mask on diagonal tile
        if (kt == qt) {
            #pragma unroll
            for (int i = 0; i < 4; i++)
                #pragma unroll
                for (int j = 0; j < 4; j++)
                    if (c0 + j > r0 + i) S[i][j] = -1e30f;
        }

        // online softmax update (row groups = 16 lanes with same ty)
        float m_old[4], m_new[4], scl[4], rsum[4], rss[4];
        #pragma unroll
        for (int i = 0; i < 4; i++) {
            float rmax = fmaxf(fmaxf(S[i][0], S[i][1]), fmaxf(S[i][2], S[i][3]));
            #pragma unroll
            for (int o = 8; o; o >>= 1)
                rmax = fmaxf(rmax, __shfl_xor_sync(0xffffffffu, rmax, o));
            m_old[i] = sm_m[r0 + i];
            m_new[i] = fmaxf(m_old[i], rmax);
            scl[i]   = __expf(m_old[i] - m_new[i]);
            rsum[i] = 0.f; rss[i] = 0.f;
            #pragma unroll
            for (int j = 0; j < 4; j++) {
                float p = __expf(S[i][j] - m_new[i]);
                Ps[(r0 + i) * FS + c0 + j] = p;
                rsum[i] += p;
                rss[i]  += p * S[i][j];   // p==0 for masked, finite S -> 0
            }
            #pragma unroll
            for (int o = 8; o; o >>= 1) {
                rsum[i] += __shfl_xor_sync(0xffffffffu, rsum[i], o);
                rss[i]  += __shfl_xor_sync(0xffffffffu, rss[i],  o);
            }
        }
        if (tx == 0) {
            #pragma unroll
            for (int i = 0; i < 4; i++) {
                int r = r0 + i;
                sm_l[r]  = sm_l[r]  * scl[i] + rsum[i];
                sm_ss[r] = sm_ss[r] * scl[i] + rss[i];
                sm_m[r]  = m_new[i];
                sm_sc[r] = scl[i];
            }
        }
        __syncthreads();

        // rescale O and accumulate P @ V
        #pragma unroll
        for (int i = 0; i < 4; i++) {
            float sc = sm_sc[r0 + i];
            #pragma unroll
            for (int j = 0; j < 4; j++) O[i][j] *= sc;
        }
        #pragma unroll 4
        for (int c = 0; c < 64; c++) {
            float p0 = Ps[(r0 + 0) * FS + c];
            float p1 = Ps[(r0 + 1) * FS + c];
            float p2 = Ps[(r0 + 2) * FS + c];
            float p3 = Ps[(r0 + 3) * FS + c];
            float4 vv = *(const float4*)&Vs[c * FS + c0];
            O[0][0] += p0 * vv.x; O[0][1] += p0 * vv.y; O[0][2] += p0 * vv.z; O[0][3] += p0 * vv.w;
            O[1][0] += p1 * vv.x; O[1][1] += p1 * vv.y; O[1][2] += p1 * vv.z; O[1][3] += p1 * vv.w;
            O[2][0] += p2 * vv.x; O[2][1] += p2 * vv.y; O[2][2] += p2 * vv.z; O[2][3] += p2 * vv.w;
            O[3][0] += p3 * vv.x; O[3][1] += p3 * vv.y; O[3][2] += p3 * vv.z; O[3][3] += p3 * vv.w;
        }
        __syncthreads();
    }

    // finalize: y = O / l, written to (B,T,C) layout
    #pragma unroll
    for (int i = 0; i < 4; i++) {
        int r = r0 + i;
        float linv = 1.0f / sm_l[r];
        int t = qt * 64 + r;
        float4 o4 = make_float4(O[i][0] * linv, O[i][1] * linv,
                                O[i][2] * linv, O[i][3] * linv);
        *(float4*)(Y + ((long)(b * Tc + t) * Cc) + h * 64 + c0) = o4;
    }

    // entropy: one thread per row
    if (tid < 64) {
        float l = sm_l[tid];
        float Hrow = sm_m[tid] + logf(l) - sm_ss[tid] / l;
        atomicAdd(ent, Hrow * (1.0f / (float)(Bc * Hc * Tc)));
    }
}

// ---------------------------------------------------------------------------
extern "C" void kernel_launch(void* const* d_in, const int* in_sizes, int n_in,
                              void* d_out, int out_size)
{
    const float* x      = (const float*)d_in[0];
    const float* ln1w   = (const float*)d_in[1];
    const float* ln1b   = (const float*)d_in[2];
    const float* w_attn = (const float*)d_in[3];
    const float* b_attn = (const float*)d_in[4];
    const float* w_proj = (const float*)d_in[5];
    const float* b_proj = (const float*)d_in[6];
    const float* ln2w   = (const float*)d_in[7];
    const float* ln2b   = (const float*)d_in[8];
    const float* w_fc   = (const float*)d_in[9];
    const float* b_fc   = (const float*)d_in[10];
    const float* w_mlp  = (const float*)d_in[11];
    const float* b_mlp  = (const float*)d_in[12];

    float* out   = (float*)d_out;
    float* x1    = out;            // x output region (also residual scratch)
    float* ent   = out + XS;       // scalar entropy
    float* presK = out + XS + 1;   // present[0]  (NOT 16B aligned -- scalar only)
    float* presV = presK + PRES;   // present[1]  (NOT 16B aligned -- scalar only)

    float *ph, *pq, *pk, *pv, *pa;
    cudaGetSymbolAddress((void**)&ph, g_h);
    cudaGetSymbolAddress((void**)&pq, g_q);
    cudaGetSymbolAddress((void**)&pk, g_k);
    cudaGetSymbolAddress((void**)&pv, g_v);
    cudaGetSymbolAddress((void**)&pa, g_a);
    cudaFuncSetAttribute(flash_kernel,
                         cudaFuncAttributeMaxDynamicSharedMemorySize, FLASH_SMEM);

    zero_ent_kernel<<<1, 1>>>(ent);

    // h = LN1(x)
    ln_kernel<<<Mrows, 256>>>(x, ln1w, ln1b, ph);

    // qkv = h @ w_attn^T + b_attn
    //   q -> g_q; k -> g_k + present[0]; v -> g_v + present[1]   (B,H,T,HD)
    {
        dim3 g(3 * Cc / 128, Mrows / 128);
        gemm_kernel<0><<<g, 256>>>(ph, w_attn, b_attn, nullptr,
                                   pq, pk, pv, presK, presV, Cc, 3 * Cc);
    }

    // flash attention: y -> g_h (reused), entropy -> ent
    {
        dim3 g(Tc / 64, Hc, Bc);
        flash_kernel<<<g, 256, FLASH_SMEM>>>(pq, pk, pv, ph, ent);
    }

    // x1 = x + y @ w_proj^T + b_proj
    {
        dim3 g(Cc / 128, Mrows / 128);
        gemm_kernel<1><<<g, 256>>>(ph, w_proj, b_proj, x,
                                   x1, nullptr, nullptr, nullptr, nullptr, Cc, Cc);
    }

    // h2 = LN2(x1) -> g_h
    ln_kernel<<<Mrows, 256>>>(x1, ln2w, ln2b, ph);

    // a = gelu(h2 @ w_fc^T + b_fc) -> g_a
    {
        dim3 g(4 * Cc / 128, Mrows / 128);
        gemm_kernel<2><<<g, 256>>>(ph, w_fc, b_fc, nullptr,
                                   pa, nullptr, nullptr, nullptr, nullptr, Cc, 4 * Cc);
    }

    // x_out = x1 + a @ w_mlp^T + b_mlp  (in-place on d_out x region)
    {
        dim3 g(Cc / 128, Mrows / 128);
        gemm_kernel<1><<<g, 256>>>(pa, w_mlp, b_mlp, x1,
                                   x1, nullptr, nullptr, nullptr, nullptr, 4 * Cc, Cc);
    }
}

// round 3
// speedup vs baseline: 1.5254x; 1.5254x over previous
#include <cuda_runtime.h>
#include <math.h>

// ---------------------------------------------------------------------------
// GPT transformer block. GEMMs on tf32 tensor cores (mma.sync), flash fp32.
//   B=2, T=2048, C=1024, H=16, HD=64
// Output layout (float32): [ x (B*T*C) | att_entropy (1) | present (2*B*H*T*HD) ]
// present region starts at float offset XS+1 -> NOT 16B aligned (scalar only).
// ---------------------------------------------------------------------------

namespace {
constexpr int Bc = 2, Tc = 2048, Cc = 1024, Hc = 16, HDc = 64;
constexpr int Mrows = Bc * Tc;            // 4096
constexpr int XS    = Bc * Tc * Cc;       // 4194304
constexpr int PRES  = Bc * Hc * Tc * HDc; // 4194304
constexpr int FS    = 68;                 // flash smem row stride (pad)
constexpr int FLASH_SMEM = (4 * 64 * FS + 256) * 4; // 70656 B

constexpr int TS = 33;                    // gemm smem row stride (32 + 1 pad)
constexpr int GEMM_SMEM = 4 * 128 * TS * 4; // 2 tiles x 2 buffers = 67584 B
}

// scratch (device globals -- no allocations allowed)
__device__ float g_h[Mrows * Cc];       // LN outputs / attention y (reused)
__device__ float g_q[PRES];             // Q in (B,H,T,HD)
__device__ float g_k[PRES];             // K in (B,H,T,HD) (aligned copy)
__device__ float g_v[PRES];             // V in (B,H,T,HD) (aligned copy)
__device__ float g_a[Mrows * 4 * Cc];   // FC activation (B,T,4C)

// ---------------------------------------------------------------------------
__global__ void zero_ent_kernel(float* e) { *e = 0.0f; }

// ---------------------------------------------------------------------------
// LayerNorm: one block per row, C=1024, 256 threads
__global__ void ln_kernel(const float* __restrict__ x,
                          const float* __restrict__ w,
                          const float* __restrict__ b,
                          float* __restrict__ out)
{
    int row = blockIdx.x;
    const float* xr = x + (long)row * Cc;
    float s = 0.f, s2 = 0.f;
    for (int i = threadIdx.x; i < Cc; i += 256) {
        float v = xr[i];
        s += v; s2 += v * v;
    }
    __shared__ float rs[32], rs2[32];
    #pragma unroll
    for (int o = 16; o; o >>= 1) {
        s  += __shfl_xor_sync(0xffffffffu, s,  o);
        s2 += __shfl_xor_sync(0xffffffffu, s2, o);
    }
    int lane = threadIdx.x & 31, wid = threadIdx.x >> 5;
    if (lane == 0) { rs[wid] = s; rs2[wid] = s2; }
    __syncthreads();
    if (wid == 0) {
        s  = (lane < 8) ? rs[lane]  : 0.f;
        s2 = (lane < 8) ? rs2[lane] : 0.f;
        #pragma unroll
        for (int o = 4; o; o >>= 1) {
            s  += __shfl_xor_sync(0xffffffffu, s,  o);
            s2 += __shfl_xor_sync(0xffffffffu, s2, o);
        }
        if (lane == 0) { rs[0] = s; rs2[0] = s2; }
    }
    __syncthreads();
    float mean = rs[0] * (1.0f / Cc);
    float var  = rs2[0] * (1.0f / Cc) - mean * mean;
    float inv  = rsqrtf(var + 1e-5f);
    float* o = out + (long)row * Cc;
    for (int i = threadIdx.x; i < Cc; i += 256)
        o[i] = (xr[i] - mean) * inv * w[i] + b[i];
}

// ---------------------------------------------------------------------------
__device__ __forceinline__ float gelu_f(float v) {
    const float c = 0.7978845608028654f;
    float u = c * (v + 0.044715f * v * v * v);
    return 0.5f * v * (1.0f + tanhf(u));
}

__device__ __forceinline__ unsigned f2tf32(float f) {
    unsigned u;
    asm("cvt.rna.tf32.f32 %0, %1;" : "=r"(u) : "f"(f));
    return u;
}

__device__ __forceinline__ void mma_tf32(float* c, const unsigned* a, const unsigned* b) {
    asm volatile(
        "mma.sync.aligned.m16n8k8.row.col.f32.tf32.tf32.f32 "
        "{%0,%1,%2,%3},{%4,%5,%6,%7},{%8,%9},{%0,%1,%2,%3};"
        : "+f"(c[0]), "+f"(c[1]), "+f"(c[2]), "+f"(c[3])
        : "r"(a[0]), "r"(a[1]), "r"(a[2]), "r"(a[3]), "r"(b[0]), "r"(b[1]));
}

// ---------------------------------------------------------------------------
// tf32 tensor-core GEMM: C[M,N] = A[M,K] @ W[N,K]^T (+bias, +epilogue)
// 128x128x32 CTA tile, 8 warps (2m x 4n), 64x32 warp tile, m16n8k8 MMAs,
// double-buffered smem, cvt.rna tf32 on fill.
// EPI: 0 = QKV scatter (q->g_q; k->g_k+present; v->g_v+present, (B,H,T,HD))
//      1 = out = acc + bias + res
//      2 = out = gelu(acc + bias)
template <int EPI>
__global__ __launch_bounds__(256)
void gemm_tf32_kernel(const float* __restrict__ A,
                      const float* __restrict__ W,
                      const float* __restrict__ bias,
                      const float* __restrict__ res,
                      float* __restrict__ outp,
                      float* __restrict__ out_k,
                      float* __restrict__ out_v,
                      float* __restrict__ pres_k,
                      float* __restrict__ pres_v,
                      int K, int N)
{
    extern __shared__ unsigned su[];
    unsigned* sA0 = su;
    unsigned* sA1 = su + 128 * TS;
    unsigned* sW0 = su + 2 * 128 * TS;
    unsigned* sW1 = su + 3 * 128 * TS;

    int tid = threadIdx.x;
    int mbase = blockIdx.y * 128, nbase = blockIdx.x * 128;
    int wid = tid >> 5, lane = tid & 31;
    int g = lane >> 2, tig = lane & 3;
    int wm = wid >> 2, wn = wid & 3;          // 2 x 4 warp grid
    int moff = wm * 64, noff = wn * 32;

    float acc[4][4][4] = {};                  // [mfrag][nfrag][c0..c3]

    // per-thread load slots: 4 float4 of A, 4 of W per 128x32 tile
    int lr[4], lc[4];
    #pragma unroll
    for (int i = 0; i < 4; i++) {
        int id = tid + i * 256;
        lr[i] = id >> 3;
        lc[i] = (id & 7) * 4;
    }

    float4 pa[4], pw[4];

    // prologue: tile 0
    #pragma unroll
    for (int i = 0; i < 4; i++) {
        pa[i] = *(const float4*)(A + (long)(mbase + lr[i]) * K + lc[i]);
        pw[i] = *(const float4*)(W + (long)(nbase + lr[i]) * K + lc[i]);
    }
    #pragma unroll
    for (int i = 0; i < 4; i++) {
        unsigned* a = sA0 + lr[i] * TS + lc[i];
        a[0] = f2tf32(pa[i].x); a[1] = f2tf32(pa[i].y);
        a[2] = f2tf32(pa[i].z); a[3] = f2tf32(pa[i].w);
        unsigned* w = sW0 + lr[i] * TS + lc[i];
        w[0] = f2tf32(pw[i].x); w[1] = f2tf32(pw[i].y);
        w[2] = f2tf32(pw[i].z); w[3] = f2tf32(pw[i].w);
    }
    __syncthreads();

    int nIter = K >> 5;
    for (int it = 0; it < nIter; it++) {
        unsigned* cA = (it & 1) ? sA1 : sA0;
        unsigned* cW = (it & 1) ? sW1 : sW0;
        unsigned* nA = (it & 1) ? sA0 : sA1;
        unsigned* nW = (it & 1) ? sW0 : sW1;
        bool more = (it + 1 < nIter);

        if (more) {
            int k0 = (it + 1) << 5;
            #pragma unroll
            for (int i = 0; i < 4; i++) {
                pa[i] = *(const float4*)(A + (long)(mbase + lr[i]) * K + k0 + lc[i]);
                pw[i] = *(const float4*)(W + (long)(nbase + lr[i]) * K + k0 + lc[i]);
            }
        }

        // compute on current buffer: 4 k-steps of 8
        #pragma unroll
        for (int x = 0; x < 4; x++) {
            int kk = x * 8;
            unsigned afr[4][4], bfr[4][2];
            #pragma unroll
            for (int mf = 0; mf < 4; mf++) {
                const unsigned* p = cA + (moff + mf * 16 + g) * TS + kk + tig;
                afr[mf][0] = p[0];
                afr[mf][1] = p[8 * TS];
                afr[mf][2] = p[4];
                afr[mf][3] = p[8 * TS + 4];
            }
            #pragma unroll
            for (int nf = 0; nf < 4; nf++) {
                const unsigned* p = cW + (noff + nf * 8 + g) * TS + kk + tig;
                bfr[nf][0] = p[0];
                bfr[nf][1] = p[4];
            }
            #pragma unroll
            for (int mf = 0; mf < 4; mf++)
                #pragma unroll
                for (int nf = 0; nf < 4; nf++)
                    mma_tf32(acc[mf][nf], afr[mf], bfr[nf]);
        }

        if (more) {
            #pragma unroll
            for (int i = 0; i < 4; i++) {
                unsigned* a = nA + lr[i] * TS + lc[i];
                a[0] = f2tf32(pa[i].x); a[1] = f2tf32(pa[i].y);
                a[2] = f2tf32(pa[i].z); a[3] = f2tf32(pa[i].w);
                unsigned* w = nW + lr[i] * TS + lc[i];
                w[0] = f2tf32(pw[i].x); w[1] = f2tf32(pw[i].y);
                w[2] = f2tf32(pw[i].z); w[3] = f2tf32(pw[i].w);
            }
        }
        __syncthreads();
    }

    // ---- epilogue ----
    if (EPI == 0) {
        int region = nbase >> 10;  // 0=q, 1=k, 2=v (tile never straddles)
        float* dst  = (region == 0) ? g_q : (region == 1) ? out_k  : out_v;
        float* dst2 = (region == 0) ? (float*)0
                    : (region == 1) ? pres_k : pres_v;
        if (region == 0) dst = outp;
        #pragma unroll
        for (int mf = 0; mf < 4; mf++) {
            #pragma unroll
            for (int i = 0; i < 2; i++) {
                int row = mbase + moff + mf * 16 + g + i * 8;
                int bidx = row >> 11;
                int t    = row & (Tc - 1);
                #pragma unroll
                for (int nf = 0; nf < 4; nf++) {
                    #pragma unroll
                    for (int j = 0; j < 2; j++) {
                        int n = nbase + noff + nf * 8 + tig * 2 + j;
                        float v = acc[mf][nf][i * 2 + j] + bias[n];
                        int nl = n & (Cc - 1);
                        int head = nl >> 6, d = nl & 63;
                        long idx = (((long)(bidx * Hc + head) * Tc) + t) * HDc + d;
                        dst[idx] = v;
                        if (dst2) dst2[idx] = v;
                    }
                }
            }
        }
    } else {
        #pragma unroll
        for (int mf = 0; mf < 4; mf++) {
            #pragma unroll
            for (int i = 0; i < 2; i++) {
                int row = mbase + moff + mf * 16 + g + i * 8;
                #pragma unroll
                for (int nf = 0; nf < 4; nf++) {
                    #pragma unroll
                    for (int j = 0; j < 2; j++) {
                        int n = nbase + noff + nf * 8 + tig * 2 + j;
                        float v = acc[mf][nf][i * 2 + j] + bias[n];
                        long idx = (long)row * N + n;
                        if (EPI == 1) v += res[idx];
                        if (EPI == 2) v = gelu_f(v);
                        outp[idx] = v;
                    }
                }
            }
        }
    }
}

// ---------------------------------------------------------------------------
// Flash attention with causal mask + entropy (fp32, unchanged from R2).
__global__ void flash_kernel(const float* __restrict__ Q,
                             const float* __restrict__ Kp,
                             const float* __restrict__ Vp,
                             float* __restrict__ Y,
                             float* __restrict__ ent)
{
    extern __shared__ float sm[];
    float* Qs   = sm;
    float* KsT  = Qs  + 64 * FS;
    float* Vs   = KsT + 64 * FS;
    float* Ps   = Vs  + 64 * FS;
    float* sm_m  = Ps + 64 * FS;
    float* sm_l  = sm_m + 64;
    float* sm_ss = sm_l + 64;
    float* sm_sc = sm_ss + 64;

    int qt = blockIdx.x, h = blockIdx.y, b = blockIdx.z;
    int tid = threadIdx.x;
    long bh = (long)(b * Hc + h);
    const float* Qg = Q  + (bh * Tc + qt * 64) * HDc;
    const float* Kg = Kp + bh * Tc * HDc;
    const float* Vg = Vp + bh * Tc * HDc;

    for (int i = tid; i < 64 * 16; i += 256) {
        int r = i >> 4, d4 = (i & 15) * 4;
        float4 v = *(const float4*)(Qg + r * 64 + d4);
        Qs[r * FS + d4 + 0] = v.x * 0.125f;
        Qs[r * FS + d4 + 1] = v.y * 0.125f;
        Qs[r * FS + d4 + 2] = v.z * 0.125f;
        Qs[r * FS + d4 + 3] = v.w * 0.125f;
    }
    if (tid < 64) { sm_m[tid] = -1e30f; sm_l[tid] = 0.f; sm_ss[tid] = 0.f; }

    int ty = tid >> 4, tx = tid & 15;
    int r0 = ty * 4, c0 = tx * 4;
    float O[4][4] = {};
    __syncthreads();

    for (int kt = 0; kt <= qt; kt++) {
        for (int i = tid; i < 64 * 16; i += 256) {
            int c = i >> 4, d4 = (i & 15) * 4;
            float4 kv = *(const float4*)(Kg + (kt * 64 + c) * 64 + d4);
            KsT[(d4 + 0) * FS + c] = kv.x;
            KsT[(d4 + 1) * FS + c] = kv.y;
            KsT[(d4 + 2) * FS + c] = kv.z;
            KsT[(d4 + 3) * FS + c] = kv.w;
            float4 vv = *(const float4*)(Vg + (kt * 64 + c) * 64 + d4);
            *(float4*)&Vs[c * FS + d4] = vv;
        }
        __syncthreads();

        float S[4][4] = {};
        #pragma unroll 4
        for (int k = 0; k < 64; k++) {
            float a0 = Qs[(r0 + 0) * FS + k];
            float a1 = Qs[(r0 + 1) * FS + k];
            float a2 = Qs[(r0 + 2) * FS + k];
            float a3 = Qs[(r0 + 3) * FS + k];
            float4 bv = *(const float4*)&KsT[k * FS + c0];
            S[0][0] += a0 * bv.x; S[0][1] += a0 * bv.y; S[0][2] += a0 * bv.z; S[0][3] += a0 * bv.w;
            S[1][0] += a1 * bv.x; S[1][1] += a1 * bv.y; S[1][2] += a1 * bv.z; S[1][3] += a1 * bv.w;
            S[2][0] += a2 * bv.x; S[2][1] += a2 * bv.y; S[2][2] += a2 * bv.z; S[2][3] += a2 * bv.w;
            S[3][0] += a3 * bv.x; S[3][1] += a3 * bv.y; S[3][2] += a3 * bv.z; S[3][3] += a3 * bv.w;
        }
        if (kt == qt) {
            #pragma unroll
            for (int i = 0; i < 4; i++)
                #pragma unroll
                for (int j = 0; j < 4; j++)
                    if (c0 + j > r0 + i) S[i][j] = -1e30f;
        }

        float m_old[4], m_new[4], scl[4], rsum[4], rss[4];
        #pragma unroll
        for (int i = 0; i < 4; i++) {
            float rmax = fmaxf(fmaxf(S[i][0], S[i][1]), fmaxf(S[i][2], S[i][3]));
            #pragma unroll
            for (int o = 8; o; o >>= 1)
                rmax = fmaxf(rmax, __shfl_xor_sync(0xffffffffu, rmax, o));
            m_old[i] = sm_m[r0 + i];
            m_new[i] = fmaxf(m_old[i], rmax);
            scl[i]   = __expf(m_old[i] - m_new[i]);
            rsum[i] = 0.f; rss[i] = 0.f;
            #pragma unroll
            for (int j = 0; j < 4; j++) {
                float p = __expf(S[i][j] - m_new[i]);
                Ps[(r0 + i) * FS + c0 + j] = p;
                rsum[i] += p;
                rss[i]  += p * S[i][j];
            }
            #pragma unroll
            for (int o = 8; o; o >>= 1) {
                rsum[i] += __shfl_xor_sync(0xffffffffu, rsum[i], o);
                rss[i]  += __shfl_xor_sync(0xffffffffu, rss[i],  o);
            }
        }
        if (tx == 0) {
            #pragma unroll
            for (int i = 0; i < 4; i++) {
                int r = r0 + i;
                sm_l[r]  = sm_l[r]  * scl[i] + rsum[i];
                sm_ss[r] = sm_ss[r] * scl[i] + rss[i];
                sm_m[r]  = m_new[i];
                sm_sc[r] = scl[i];
            }
        }
        __syncthreads();

        #pragma unroll
        for (int i = 0; i < 4; i++) {
            float sc = sm_sc[r0 + i];
            #pragma unroll
            for (int j = 0; j < 4; j++) O[i][j] *= sc;
        }
        #pragma unroll 4
        for (int c = 0; c < 64; c++) {
            float p0 = Ps[(r0 + 0) * FS + c];
            float p1 = Ps[(r0 + 1) * FS + c];
            float p2 = Ps[(r0 + 2) * FS + c];
            float p3 = Ps[(r0 + 3) * FS + c];
            float4 vv = *(const float4*)&Vs[c * FS + c0];
            O[0][0] += p0 * vv.x; O[0][1] += p0 * vv.y; O[0][2] += p0 * vv.z; O[0][3] += p0 * vv.w;
            O[1][0] += p1 * vv.x; O[1][1] += p1 * vv.y; O[1][2] += p1 * vv.z; O[1][3] += p1 * vv.w;
            O[2][0] += p2 * vv.x; O[2][1] += p2 * vv.y; O[2][2] += p2 * vv.z; O[2][3] += p2 * vv.w;
            O[3][0] += p3 * vv.x; O[3][1] += p3 * vv.y; O[3][2] += p3 * vv.z; O[3][3] += p3 * vv.w;
        }
        __syncthreads();
    }

    #pragma unroll
    for (int i = 0; i < 4; i++) {
        int r = r0 + i;
        float linv = 1.0f / sm_l[r];
        int t = qt * 64 + r;
        float4 o4 = make_float4(O[i][0] * linv, O[i][1] * linv,
                                O[i][2] * linv, O[i][3] * linv);
        *(float4*)(Y + ((long)(b * Tc + t) * Cc) + h * 64 + c0) = o4;
    }

    if (tid < 64) {
        float l = sm_l[tid];
        float Hrow = sm_m[tid] + logf(l) - sm_ss[tid] / l;
        atomicAdd(ent, Hrow * (1.0f / (float)(Bc * Hc * Tc)));
    }
}

// ---------------------------------------------------------------------------
extern "C" void kernel_launch(void* const* d_in, const int* in_sizes, int n_in,
                              void* d_out, int out_size)
{
    const float* x      = (const float*)d_in[0];
    const float* ln1w   = (const float*)d_in[1];
    const float* ln1b   = (const float*)d_in[2];
    const float* w_attn = (const float*)d_in[3];
    const float* b_attn = (const float*)d_in[4];
    const float* w_proj = (const float*)d_in[5];
    const float* b_proj = (const float*)d_in[6];
    const float* ln2w   = (const float*)d_in[7];
    const float* ln2b   = (const float*)d_in[8];
    const float* w_fc   = (const float*)d_in[9];
    const float* b_fc   = (const float*)d_in[10];
    const float* w_mlp  = (const float*)d_in[11];
    const float* b_mlp  = (const float*)d_in[12];

    float* out   = (float*)d_out;
    float* x1    = out;            // x output region
    float* ent   = out + XS;       // scalar entropy
    float* presK = out + XS + 1;   // present[0] (unaligned -- scalar only)
    float* presV = presK + PRES;   // present[1]

    float *ph, *pq, *pk, *pv, *pa;
    cudaGetSymbolAddress((void**)&ph, g_h);
    cudaGetSymbolAddress((void**)&pq, g_q);
    cudaGetSymbolAddress((void**)&pk, g_k);
    cudaGetSymbolAddress((void**)&pv, g_v);
    cudaGetSymbolAddress((void**)&pa, g_a);

    cudaFuncSetAttribute(flash_kernel,
                         cudaFuncAttributeMaxDynamicSharedMemorySize, FLASH_SMEM);
    cudaFuncSetAttribute(gemm_tf32_kernel<0>,
                         cudaFuncAttributeMaxDynamicSharedMemorySize, GEMM_SMEM);
    cudaFuncSetAttribute(gemm_tf32_kernel<1>,
                         cudaFuncAttributeMaxDynamicSharedMemorySize, GEMM_SMEM);
    cudaFuncSetAttribute(gemm_tf32_kernel<2>,
                         cudaFuncAttributeMaxDynamicSharedMemorySize, GEMM_SMEM);

    zero_ent_kernel<<<1, 1>>>(ent);

    // h = LN1(x)
    ln_kernel<<<Mrows, 256>>>(x, ln1w, ln1b, ph);

    // qkv = h @ w_attn^T + b_attn  (q->g_q; k->g_k+present; v->g_v+present)
    {
        dim3 g(3 * Cc / 128, Mrows / 128);
        gemm_tf32_kernel<0><<<g, 256, GEMM_SMEM>>>(ph, w_attn, b_attn, nullptr,
                                                   pq, pk, pv, presK, presV,
                                                   Cc, 3 * Cc);
    }

    // flash attention: y -> g_h, entropy -> ent
    {
        dim3 g(Tc / 64, Hc, Bc);
        flash_kernel<<<g, 256, FLASH_SMEM>>>(pq, pk, pv, ph, ent);
    }

    // x1 = x + y @ w_proj^T + b_proj
    {
        dim3 g(Cc / 128, Mrows / 128);
        gemm_tf32_kernel<1><<<g, 256, GEMM_SMEM>>>(ph, w_proj, b_proj, x,
                                                   x1, nullptr, nullptr, nullptr, nullptr,
                                                   Cc, Cc);
    }

    // h2 = LN2(x1) -> g_h
    ln_kernel<<<Mrows, 256>>>(x1, ln2w, ln2b, ph);

    // a = gelu(h2 @ w_fc^T + b_fc) -> g_a
    {
        dim3 g(4 * Cc / 128, Mrows / 128);
        gemm_tf32_kernel<2><<<g, 256, GEMM_SMEM>>>(ph, w_fc, b_fc, nullptr,
                                                   pa, nullptr, nullptr, nullptr, nullptr,
                                                   Cc, 4 * Cc);
    }

    // x_out = x1 + a @ w_mlp^T + b_mlp  (in-place on d_out x region)
    {
        dim3 g(Cc / 128, Mrows / 128);
        gemm_tf32_kernel<1><<<g, 256, GEMM_SMEM>>>(pa, w_mlp, b_mlp, x1,
                                                   x1, nullptr, nullptr, nullptr, nullptr,
                                                   4 * Cc, Cc);
    }
}

// round 4
// speedup vs baseline: 1.9084x; 1.2511x over previous
#include <cuda_runtime.h>
#include <math.h>

// ---------------------------------------------------------------------------
// GPT transformer block. GEMMs + flash attention on tf32 tensor cores.
//   B=2, T=2048, C=1024, H=16, HD=64
// Output layout (float32): [ x (B*T*C) | att_entropy (1) | present (2*B*H*T*HD) ]
// present region starts at float offset XS+1 -> NOT 16B aligned (scalar only).
// ---------------------------------------------------------------------------

namespace {
constexpr int Bc = 2, Tc = 2048, Cc = 1024, Hc = 16, HDc = 64;
constexpr int Mrows = Bc * Tc;            // 4096
constexpr int XS    = Bc * Tc * Cc;       // 4194304
constexpr int PRES  = Bc * Hc * Tc * HDc; // 4194304

constexpr int TS = 33;                    // gemm smem row stride (32 + 1 pad)
constexpr int GEMM_SMEM = 4 * 128 * TS * 4; // 67584 B

// flash smem strides (words). chosen so fragment loads are conflict-free:
//  68 mod 32 = 4  -> A/B frag addr banks = 4g+tig (distinct over a warp)
//  72 mod 32 = 8  -> V B-frag addr banks = 8tig+g (distinct over a warp)
constexpr int QS_ = 68, KS_ = 68, VS_ = 72, PS_ = 68;
constexpr int FLASH_SMEM = (64*QS_ + 64*KS_ + 64*VS_ + 64*PS_ + 64) * 4; // 70912 B
}

// scratch (device globals -- no allocations allowed)
__device__ float g_h[Mrows * Cc];       // LN outputs / attention y (reused)
__device__ float g_q[PRES];             // Q in (B,H,T,HD)
__device__ float g_k[PRES];             // K in (B,H,T,HD) (aligned copy)
__device__ float g_v[PRES];             // V in (B,H,T,HD) (aligned copy)
__device__ float g_a[Mrows * 4 * Cc];   // FC activation (B,T,4C)

// ---------------------------------------------------------------------------
__global__ void zero_ent_kernel(float* e) { *e = 0.0f; }

// ---------------------------------------------------------------------------
// LayerNorm: one block per row, C=1024, 256 threads
__global__ void ln_kernel(const float* __restrict__ x,
                          const float* __restrict__ w,
                          const float* __restrict__ b,
                          float* __restrict__ out)
{
    int row = blockIdx.x;
    const float* xr = x + (long)row * Cc;
    float s = 0.f, s2 = 0.f;
    for (int i = threadIdx.x; i < Cc; i += 256) {
        float v = xr[i];
        s += v; s2 += v * v;
    }
    __shared__ float rs[32], rs2[32];
    #pragma unroll
    for (int o = 16; o; o >>= 1) {
        s  += __shfl_xor_sync(0xffffffffu, s,  o);
        s2 += __shfl_xor_sync(0xffffffffu, s2, o);
    }
    int lane = threadIdx.x & 31, wid = threadIdx.x >> 5;
    if (lane == 0) { rs[wid] = s; rs2[wid] = s2; }
    __syncthreads();
    if (wid == 0) {
        s  = (lane < 8) ? rs[lane]  : 0.f;
        s2 = (lane < 8) ? rs2[lane] : 0.f;
        #pragma unroll
        for (int o = 4; o; o >>= 1) {
            s  += __shfl_xor_sync(0xffffffffu, s,  o);
            s2 += __shfl_xor_sync(0xffffffffu, s2, o);
        }
        if (lane == 0) { rs[0] = s; rs2[0] = s2; }
    }
    __syncthreads();
    float mean = rs[0] * (1.0f / Cc);
    float var  = rs2[0] * (1.0f / Cc) - mean * mean;
    float inv  = rsqrtf(var + 1e-5f);
    float* o = out + (long)row * Cc;
    for (int i = threadIdx.x; i < Cc; i += 256)
        o[i] = (xr[i] - mean) * inv * w[i] + b[i];
}

// ---------------------------------------------------------------------------
__device__ __forceinline__ float gelu_f(float v) {
    const float c = 0.7978845608028654f;
    float u = c * (v + 0.044715f * v * v * v);
    return 0.5f * v * (1.0f + tanhf(u));
}

__device__ __forceinline__ unsigned f2tf32(float f) {
    unsigned u;
    asm("cvt.rna.tf32.f32 %0, %1;" : "=r"(u) : "f"(f));
    return u;
}
__device__ __forceinline__ float tf32f(float f) {
    return __uint_as_float(f2tf32(f));
}

__device__ __forceinline__ void mma_tf32(float* c, const unsigned* a, const unsigned* b) {
    asm volatile(
        "mma.sync.aligned.m16n8k8.row.col.f32.tf32.tf32.f32 "
        "{%0,%1,%2,%3},{%4,%5,%6,%7},{%8,%9},{%0,%1,%2,%3};"
        : "+f"(c[0]), "+f"(c[1]), "+f"(c[2]), "+f"(c[3])
        : "r"(a[0]), "r"(a[1]), "r"(a[2]), "r"(a[3]), "r"(b[0]), "r"(b[1]));
}

// fast exp on the FMA pipe (no MUFU). x <= ~0. rel err ~4e-5.
__device__ __forceinline__ float fexp(float x) {
    x = fmaxf(x, -87.0f);
    float z = x * 1.442695041f;            // log2(e)
    float t = z + 12582912.0f;             // 1.5*2^23 magic: rint
    float n = t - 12582912.0f;
    float r = z - n;                       // r in [-0.5, 0.5]
    float p = 9.61812910e-3f;              // 2^r Taylor (in r, base-e coeffs of r*ln2)
    p = fmaf(p, r, 5.55041087e-2f);
    p = fmaf(p, r, 2.40226507e-1f);
    p = fmaf(p, r, 6.93147182e-1f);
    p = fmaf(p, r, 1.0f);
    return __int_as_float(__float_as_int(p) + (__float_as_int(t) << 23));
}

// ---------------------------------------------------------------------------
// tf32 tensor-core GEMM (unchanged from R3): C = A[M,K] @ W[N,K]^T (+epilogue)
template <int EPI>
__global__ __launch_bounds__(256)
void gemm_tf32_kernel(const float* __restrict__ A,
                      const float* __restrict__ W,
                      const float* __restrict__ bias,
                      const float* __restrict__ res,
                      float* __restrict__ outp,
                      float* __restrict__ out_k,
                      float* __restrict__ out_v,
                      float* __restrict__ pres_k,
                      float* __restrict__ pres_v,
                      int K, int N)
{
    extern __shared__ unsigned su[];
    unsigned* sA0 = su;
    unsigned* sA1 = su + 128 * TS;
    unsigned* sW0 = su + 2 * 128 * TS;
    unsigned* sW1 = su + 3 * 128 * TS;

    int tid = threadIdx.x;
    int mbase = blockIdx.y * 128, nbase = blockIdx.x * 128;
    int wid = tid >> 5, lane = tid & 31;
    int g = lane >> 2, tig = lane & 3;
    int wm = wid >> 2, wn = wid & 3;
    int moff = wm * 64, noff = wn * 32;

    float acc[4][4][4] = {};

    int lr[4], lc[4];
    #pragma unroll
    for (int i = 0; i < 4; i++) {
        int id = tid + i * 256;
        lr[i] = id >> 3;
        lc[i] = (id & 7) * 4;
    }

    float4 pa[4], pw[4];
    #pragma unroll
    for (int i = 0; i < 4; i++) {
        pa[i] = *(const float4*)(A + (long)(mbase + lr[i]) * K + lc[i]);
        pw[i] = *(const float4*)(W + (long)(nbase + lr[i]) * K + lc[i]);
    }
    #pragma unroll
    for (int i = 0; i < 4; i++) {
        unsigned* a = sA0 + lr[i] * TS + lc[i];
        a[0] = f2tf32(pa[i].x); a[1] = f2tf32(pa[i].y);
        a[2] = f2tf32(pa[i].z); a[3] = f2tf32(pa[i].w);
        unsigned* w = sW0 + lr[i] * TS + lc[i];
        w[0] = f2tf32(pw[i].x); w[1] = f2tf32(pw[i].y);
        w[2] = f2tf32(pw[i].z); w[3] = f2tf32(pw[i].w);
    }
    __syncthreads();

    int nIter = K >> 5;
    for (int it = 0; it < nIter; it++) {
        unsigned* cA = (it & 1) ? sA1 : sA0;
        unsigned* cW = (it & 1) ? sW1 : sW0;
        unsigned* nA = (it & 1) ? sA0 : sA1;
        unsigned* nW = (it & 1) ? sW0 : sW1;
        bool more = (it + 1 < nIter);

        if (more) {
            int k0 = (it + 1) << 5;
            #pragma unroll
            for (int i = 0; i < 4; i++) {
                pa[i] = *(const float4*)(A + (long)(mbase + lr[i]) * K + k0 + lc[i]);
                pw[i] = *(const float4*)(W + (long)(nbase + lr[i]) * K + k0 + lc[i]);
            }
        }

        #pragma unroll
        for (int x = 0; x < 4; x++) {
            int kk = x * 8;
            unsigned afr[4][4], bfr[4][2];
            #pragma unroll
            for (int mf = 0; mf < 4; mf++) {
                const unsigned* p = cA + (moff + mf * 16 + g) * TS + kk + tig;
                afr[mf][0] = p[0];
                afr[mf][1] = p[8 * TS];
                afr[mf][2] = p[4];
                afr[mf][3] = p[8 * TS + 4];
            }
            #pragma unroll
            for (int nf = 0; nf < 4; nf++) {
                const unsigned* p = cW + (noff + nf * 8 + g) * TS + kk + tig;
                bfr[nf][0] = p[0];
                bfr[nf][1] = p[4];
            }
            #pragma unroll
            for (int mf = 0; mf < 4; mf++)
                #pragma unroll
                for (int nf = 0; nf < 4; nf++)
                    mma_tf32(acc[mf][nf], afr[mf], bfr[nf]);
        }

        if (more) {
            #pragma unroll
            for (int i = 0; i < 4; i++) {
                unsigned* a = nA + lr[i] * TS + lc[i];
                a[0] = f2tf32(pa[i].x); a[1] = f2tf32(pa[i].y);
                a[2] = f2tf32(pa[i].z); a[3] = f2tf32(pa[i].w);
                unsigned* w = nW + lr[i] * TS + lc[i];
                w[0] = f2tf32(pw[i].x); w[1] = f2tf32(pw[i].y);
                w[2] = f2tf32(pw[i].z); w[3] = f2tf32(pw[i].w);
            }
        }
        __syncthreads();
    }

    if (EPI == 0) {
        int region = nbase >> 10;
        float* dst  = (region == 0) ? outp : (region == 1) ? out_k  : out_v;
        float* dst2 = (region == 0) ? (float*)0
                    : (region == 1) ? pres_k : pres_v;
        #pragma unroll
        for (int mf = 0; mf < 4; mf++) {
            #pragma unroll
            for (int i = 0; i < 2; i++) {
                int row = mbase + moff + mf * 16 + g + i * 8;
                int bidx = row >> 11;
                int t    = row & (Tc - 1);
                #pragma unroll
                for (int nf = 0; nf < 4; nf++) {
                    #pragma unroll
                    for (int j = 0; j < 2; j++) {
                        int n = nbase + noff + nf * 8 + tig * 2 + j;
                        float v = acc[mf][nf][i * 2 + j] + bias[n];
                        int nl = n & (Cc - 1);
                        int head = nl >> 6, d = nl & 63;
                        long idx = (((long)(bidx * Hc + head) * Tc) + t) * HDc + d;
                        dst[idx] = v;
                        if (dst2) dst2[idx] = v;
                    }
                }
            }
        }
    } else {
        #pragma unroll
        for (int mf = 0; mf < 4; mf++) {
            #pragma unroll
            for (int i = 0; i < 2; i++) {
                int row = mbase + moff + mf * 16 + g + i * 8;
                #pragma unroll
                for (int nf = 0; nf < 4; nf++) {
                    #pragma unroll
                    for (int j = 0; j < 2; j++) {
                        int n = nbase + noff + nf * 8 + tig * 2 + j;
                        float v = acc[mf][nf][i * 2 + j] + bias[n];
                        long idx = (long)row * N + n;
                        if (EPI == 1) v += res[idx];
                        if (EPI == 2) v = gelu_f(v);
                        outp[idx] = v;
                    }
                }
            }
        }
    }
}

// ---------------------------------------------------------------------------
// Flash attention on tf32 tensor cores + FMA-pipe exp. Causal + entropy.
// CTA: 64 q-rows, 4 warps (128 thr), each warp 16 rows x 64 keys per tile.
// Register softmax stats per thread (rows g, g+8 of its warp stripe,
// replicated across the 4 quad lanes; reduced by shfl_xor 1,2).
__global__ __launch_bounds__(128, 3)
void flash_mma_kernel(const float* __restrict__ Q,
                      const float* __restrict__ Kp,
                      const float* __restrict__ Vp,
                      float* __restrict__ Y,
                      float* __restrict__ ent)
{
    extern __shared__ float sm[];
    float* Qs = sm;                 // [64][QS_]  rows x dims (tf32 bits)
    float* Ks = Qs + 64 * QS_;      // [64][KS_]  keys x dims (tf32 bits)
    float* Vs = Ks + 64 * KS_;      // [64][VS_]  keys x dims (tf32 bits)
    float* Ps = Vs + 64 * VS_;      // [64][PS_]  rows x keys (tf32 bits)
    float* Hs = Ps + 64 * PS_;      // [64] per-row entropy

    int qt = blockIdx.x, h = blockIdx.y, b = blockIdx.z;
    int tid = threadIdx.x, wid = tid >> 5, lane = tid & 31;
    int g = lane >> 2, tig = lane & 3;
    int wrow = wid * 16;
    long bh = (long)(b * Hc + h);
    const float* Qg = Q  + (bh * Tc + qt * 64) * HDc;
    const float* Kg = Kp + bh * Tc * HDc;
    const float* Vg = Vp + bh * Tc * HDc;

    // stage Q (scaled by 1/sqrt(64), tf32-rounded)
    #pragma unroll
    for (int it = 0; it < 8; it++) {
        int idx = it * 128 + tid;
        int r = idx >> 4, c4 = (idx & 15) << 2;
        float4 v = *(const float4*)(Qg + r * 64 + c4);
        float4 o;
        o.x = tf32f(v.x * 0.125f); o.y = tf32f(v.y * 0.125f);
        o.z = tf32f(v.z * 0.125f); o.w = tf32f(v.w * 0.125f);
        *(float4*)(Qs + r * QS_ + c4) = o;
    }

    float m0 = -1e30f, m1 = -1e30f, l0 = 0.f, l1 = 0.f, ss0 = 0.f, ss1 = 0.f;
    float o_[8][4];
    #pragma unroll
    for (int i = 0; i < 8; i++)
        o_[i][0] = o_[i][1] = o_[i][2] = o_[i][3] = 0.f;

    int row_g0 = qt * 64 + wrow + g;
    int row_g1 = row_g0 + 8;

    for (int kt = 0; kt <= qt; kt++) {
        __syncthreads();   // prior O-MMA consumers done with Ks/Vs (and Q visible)
        #pragma unroll
        for (int it = 0; it < 8; it++) {
            int idx = it * 128 + tid;
            int r = idx >> 4, c4 = (idx & 15) << 2;
            float4 kv = *(const float4*)(Kg + (kt * 64 + r) * 64 + c4);
            float4 ko;
            ko.x = tf32f(kv.x); ko.y = tf32f(kv.y);
            ko.z = tf32f(kv.z); ko.w = tf32f(kv.w);
            *(float4*)(Ks + r * KS_ + c4) = ko;
            float4 vv = *(const float4*)(Vg + (kt * 64 + r) * 64 + c4);
            float4 vo;
            vo.x = tf32f(vv.x); vo.y = tf32f(vv.y);
            vo.z = tf32f(vv.z); vo.w = tf32f(vv.w);
            *(float4*)(Vs + r * VS_ + c4) = vo;
        }
        __syncthreads();

        // ---- S = Q @ K^T ----
        float s[8][4];
        #pragma unroll
        for (int nf = 0; nf < 8; nf++)
            s[nf][0] = s[nf][1] = s[nf][2] = s[nf][3] = 0.f;

        #pragma unroll
        for (int ks = 0; ks < 8; ks++) {
            int kk = ks * 8;
            unsigned a[4];
            const float* qp = Qs + (wrow + g) * QS_ + kk + tig;
            a[0] = __float_as_uint(qp[0]);
            a[1] = __float_as_uint(qp[8 * QS_]);
            a[2] = __float_as_uint(qp[4]);
            a[3] = __float_as_uint(qp[8 * QS_ + 4]);
            #pragma unroll
            for (int nf = 0; nf < 8; nf++) {
                const float* kp2 = Ks + (nf * 8 + g) * KS_ + kk + tig;
                unsigned bb[2] = { __float_as_uint(kp2[0]), __float_as_uint(kp2[4]) };
                mma_tf32(s[nf], a, bb);
            }
        }

        // causal mask (diagonal tile only)
        if (kt == qt) {
            #pragma unroll
            for (int nf = 0; nf < 8; nf++) {
                int c = kt * 64 + nf * 8 + 2 * tig;
                if (c     > row_g0) s[nf][0] = -1e30f;
                if (c + 1 > row_g0) s[nf][1] = -1e30f;
                if (c     > row_g1) s[nf][2] = -1e30f;
                if (c + 1 > row_g1) s[nf][3] = -1e30f;
            }
        }

        // ---- online softmax (register stats, quad-replicated) ----
        float rm0 = -1e30f, rm1 = -1e30f;
        #pragma unroll
        for (int nf = 0; nf < 8; nf++) {
            rm0 = fmaxf(rm0, fmaxf(s[nf][0], s[nf][1]));
            rm1 = fmaxf(rm1, fmaxf(s[nf][2], s[nf][3]));
        }
        rm0 = fmaxf(rm0, __shfl_xor_sync(0xffffffffu, rm0, 1));
        rm0 = fmaxf(rm0, __shfl_xor_sync(0xffffffffu, rm0, 2));
        rm1 = fmaxf(rm1, __shfl_xor_sync(0xffffffffu, rm1, 1));
        rm1 = fmaxf(rm1, __shfl_xor_sync(0xffffffffu, rm1, 2));

        float mn0 = fmaxf(m0, rm0), mn1 = fmaxf(m1, rm1);
        float sc0 = fexp(m0 - mn0), sc1 = fexp(m1 - mn1);

        float rs0 = 0.f, rs1 = 0.f, rw0 = 0.f, rw1 = 0.f;
        float* prow0 = Ps + (wrow + g) * PS_ + 2 * tig;
        float* prow1 = prow0 + 8 * PS_;
        #pragma unroll
        for (int nf = 0; nf < 8; nf++) {
            float p00 = fexp(s[nf][0] - mn0), p01 = fexp(s[nf][1] - mn0);
            float p10 = fexp(s[nf][2] - mn1), p11 = fexp(s[nf][3] - mn1);
            rs0 += p00 + p01; rw0 += p00 * s[nf][0] + p01 * s[nf][1];
            rs1 += p10 + p11; rw1 += p10 * s[nf][2] + p11 * s[nf][3];
            *(float2*)(prow0 + nf * 8) = make_float2(tf32f(p00), tf32f(p01));
            *(float2*)(prow1 + nf * 8) = make_float2(tf32f(p10), tf32f(p11));
        }
        #pragma unroll
        for (int o = 1; o <= 2; o <<= 1) {
            rs0 += __shfl_xor_sync(0xffffffffu, rs0, o);
            rw0 += __shfl_xor_sync(0xffffffffu, rw0, o);
            rs1 += __shfl_xor_sync(0xffffffffu, rs1, o);
            rw1 += __shfl_xor_sync(0xffffffffu, rw1, o);
        }
        l0 = l0 * sc0 + rs0;  ss0 = ss0 * sc0 + rw0;  m0 = mn0;
        l1 = l1 * sc1 + rs1;  ss1 = ss1 * sc1 + rw1;  m1 = mn1;

        #pragma unroll
        for (int nf = 0; nf < 8; nf++) {
            o_[nf][0] *= sc0; o_[nf][1] *= sc0;
            o_[nf][2] *= sc1; o_[nf][3] *= sc1;
        }
        __syncwarp();   // P rows (own warp) visible for O-MMA

        // ---- O += P @ V ----
        #pragma unroll
        for (int ks = 0; ks < 8; ks++) {
            int kk = ks * 8;
            unsigned a[4];
            const float* pp = Ps + (wrow + g) * PS_ + kk + tig;
            a[0] = __float_as_uint(pp[0]);
            a[1] = __float_as_uint(pp[8 * PS_]);
            a[2] = __float_as_uint(pp[4]);
            a[3] = __float_as_uint(pp[8 * PS_ + 4]);
            const float* vbase = Vs + (kk + tig) * VS_ + g;
            #pragma unroll
            for (int nf = 0; nf < 8; nf++) {
                unsigned bb[2] = { __float_as_uint(vbase[nf * 8]),
                                   __float_as_uint(vbase[4 * VS_ + nf * 8]) };
                mma_tf32(o_[nf], a, bb);
            }
        }
    }

    // ---- finalize: y = O / l -> (B,T,C) ----
    float li0 = 1.f / l0, li1 = 1.f / l1;
    int t0 = qt * 64 + wrow + g;
    float* y0 = Y + ((long)(b * Tc + t0)) * Cc + h * 64 + 2 * tig;
    float* y1 = y0 + 8 * Cc;
    #pragma unroll
    for (int nf = 0; nf < 8; nf++) {
        *(float2*)(y0 + nf * 8) = make_float2(o_[nf][0] * li0, o_[nf][1] * li0);
        *(float2*)(y1 + nf * 8) = make_float2(o_[nf][2] * li1, o_[nf][3] * li1);
    }

    // entropy: H = m + log(l) - ss/l per row
    if (tig == 0) {
        Hs[wrow + g]     = m0 + logf(l0) - ss0 / l0;
        Hs[wrow + g + 8] = m1 + logf(l1) - ss1 / l1;
    }
    __syncthreads();
    if (tid == 0) {
        float sum = 0.f;
        #pragma unroll 8
        for (int i = 0; i < 64; i++) sum += Hs[i];
        atomicAdd(ent, sum * (1.0f / (float)(Bc * Hc * Tc)));
    }
}

// ---------------------------------------------------------------------------
extern "C" void kernel_launch(void* const* d_in, const int* in_sizes, int n_in,
                              void* d_out, int out_size)
{
    const float* x      = (const float*)d_in[0];
    const float* ln1w   = (const float*)d_in[1];
    const float* ln1b   = (const float*)d_in[2];
    const float* w_attn = (const float*)d_in[3];
    const float* b_attn = (const float*)d_in[4];
    const float* w_proj = (const float*)d_in[5];
    const float* b_proj = (const float*)d_in[6];
    const float* ln2w   = (const float*)d_in[7];
    const float* ln2b   = (const float*)d_in[8];
    const float* w_fc   = (const float*)d_in[9];
    const float* b_fc   = (const float*)d_in[10];
    const float* w_mlp  = (const float*)d_in[11];
    const float* b_mlp  = (const float*)d_in[12];

    float* out   = (float*)d_out;
    float* x1    = out;            // x output region
    float* ent   = out + XS;       // scalar entropy
    float* presK = out + XS + 1;   // present[0] (unaligned -- scalar only)
    float* presV = presK + PRES;   // present[1]

    float *ph, *pq, *pk, *pv, *pa;
    cudaGetSymbolAddress((void**)&ph, g_h);
    cudaGetSymbolAddress((void**)&pq, g_q);
    cudaGetSymbolAddress((void**)&pk, g_k);
    cudaGetSymbolAddress((void**)&pv, g_v);
    cudaGetSymbolAddress((void**)&pa, g_a);

    cudaFuncSetAttribute(flash_mma_kernel,
                         cudaFuncAttributeMaxDynamicSharedMemorySize, FLASH_SMEM);
    cudaFuncSetAttribute(gemm_tf32_kernel<0>,
                         cudaFuncAttributeMaxDynamicSharedMemorySize, GEMM_SMEM);
    cudaFuncSetAttribute(gemm_tf32_kernel<1>,
                         cudaFuncAttributeMaxDynamicSharedMemorySize, GEMM_SMEM);
    cudaFuncSetAttribute(gemm_tf32_kernel<2>,
                         cudaFuncAttributeMaxDynamicSharedMemorySize, GEMM_SMEM);

    zero_ent_kernel<<<1, 1>>>(ent);

    // h = LN1(x)
    ln_kernel<<<Mrows, 256>>>(x, ln1w, ln1b, ph);

    // qkv = h @ w_attn^T + b_attn  (q->g_q; k->g_k+present; v->g_v+present)
    {
        dim3 g(3 * Cc / 128, Mrows / 128);
        gemm_tf32_kernel<0><<<g, 256, GEMM_SMEM>>>(ph, w_attn, b_attn, nullptr,
                                                   pq, pk, pv, presK, presV,
                                                   Cc, 3 * Cc);
    }

    // flash attention (tensor cores): y -> g_h, entropy -> ent
    {
        dim3 g(Tc / 64, Hc, Bc);
        flash_mma_kernel<<<g, 128, FLASH_SMEM>>>(pq, pk, pv, ph, ent);
    }

    // x1 = x + y @ w_proj^T + b_proj
    {
        dim3 g(Cc / 128, Mrows / 128);
        gemm_tf32_kernel<1><<<g, 256, GEMM_SMEM>>>(ph, w_proj, b_proj, x,
                                                   x1, nullptr, nullptr, nullptr, nullptr,
                                                   Cc, Cc);
    }

    // h2 = LN2(x1) -> g_h
    ln_kernel<<<Mrows, 256>>>(x1, ln2w, ln2b, ph);

    // a = gelu(h2 @ w_fc^T + b_fc) -> g_a
    {
        dim3 g(4 * Cc / 128, Mrows / 128);
        gemm_tf32_kernel<2><<<g, 256, GEMM_SMEM>>>(ph, w_fc, b_fc, nullptr,
                                                   pa, nullptr, nullptr, nullptr, nullptr,
                                                   Cc, 4 * Cc);
    }

    // x_out = x1 + a @ w_mlp^T + b_mlp  (in-place on d_out x region)
    {
        dim3 g(Cc / 128, Mrows / 128);
        gemm_tf32_kernel<1><<<g, 256, GEMM_SMEM>>>(pa, w_mlp, b_mlp, x1,
                                                   x1, nullptr, nullptr, nullptr, nullptr,
                                                   4 * Cc, Cc);
    }
}

// round 6
// speedup vs baseline: 3.1622x; 1.6570x over previous
#include <cuda_runtime.h>
#include <math.h>
#include <stdint.h>

// ---------------------------------------------------------------------------
// GPT transformer block. GEMMs + flash on tf32 mma.sync (legacy HMMA pipe --
// tcgen05 is unavailable: harness targets sm_103 without the 'a' feature set).
// GEMM feeding via cp.async 4-stage pipeline; tf32 rounding hoisted to
// producers (LN / flash / GELU) and a one-shot weight-convert pass.
//   B=2, T=2048, C=1024, H=16, HD=64
// Output layout (float32): [ x (B*T*C) | att_entropy (1) | present (2*B*H*T*HD) ]
// present region starts at float offset XS+1 -> NOT 16B aligned (scalar only).
// ---------------------------------------------------------------------------

namespace {
constexpr int Bc = 2, Tc = 2048, Cc = 1024, Hc = 16, HDc = 64;
constexpr int Mrows = Bc * Tc;            // 4096
constexpr int XS    = Bc * Tc * Cc;       // 4194304
constexpr int PRES  = Bc * Hc * Tc * HDc; // 4194304

// flash smem strides (words) -- conflict-free fragment loads (see R4)
constexpr int QS_ = 68, KS_ = 68, VS_ = 72, PS_ = 68;
constexpr int FLASH_SMEM = (64*QS_ + 64*KS_ + 64*VS_ + 64*PS_ + 64) * 4; // 70912 B

// cp.async GEMM: 128x128 CTA tile, BK=32, 4 pipeline stages
constexpr int TSg  = 36;                   // row stride words (144B, 16B mult)
constexpr int STG  = 4;
constexpr int ATILE = 128 * TSg;           // words per operand per stage
constexpr int GEMM_SMEM = STG * 2 * ATILE * 4; // 147456 B
}

// scratch (device globals -- no allocations allowed)
__device__ float g_h[Mrows * Cc];       // LN outputs / attention y (reused)
__device__ float g_q[PRES];             // Q in (B,H,T,HD)
__device__ float g_k[PRES];             // K in (B,H,T,HD)
__device__ float g_v[PRES];             // V in (B,H,T,HD)
__device__ float g_a[Mrows * 4 * Cc];   // FC activation (B,T,4C)
__device__ float g_wa[3 * Cc * Cc];     // tf32-rounded w_attn
__device__ float g_wp[Cc * Cc];         // tf32-rounded w_proj
__device__ float g_wf[4 * Cc * Cc];     // tf32-rounded w_fc
__device__ float g_wm[4 * Cc * Cc];     // tf32-rounded w_mlp

// ---------------------------------------------------------------------------
__device__ __forceinline__ uint32_t smem_u32(const void* p) {
    uint32_t a;
    asm("{ .reg .u64 t; cvta.to.shared.u64 t, %1; cvt.u32.u64 %0, t; }"
        : "=r"(a) : "l"(p));
    return a;
}
__device__ __forceinline__ void cp_async16(uint32_t dst, const void* src) {
    asm volatile("cp.async.cg.shared.global [%0], [%1], 16;"
                 :: "r"(dst), "l"(src));
}
#define CP_COMMIT() asm volatile("cp.async.commit_group;" ::: "memory")
#define CP_WAIT2()  asm volatile("cp.async.wait_group 2;"  ::: "memory")

__device__ __forceinline__ unsigned f2tf32(float f) {
    unsigned u;
    asm("cvt.rna.tf32.f32 %0, %1;" : "=r"(u) : "f"(f));
    return u;
}
__device__ __forceinline__ float tf32f(float f) {
    return __uint_as_float(f2tf32(f));
}
__device__ __forceinline__ void mma_tf32(float* c, const unsigned* a, const unsigned* b) {
    asm volatile(
        "mma.sync.aligned.m16n8k8.row.col.f32.tf32.tf32.f32 "
        "{%0,%1,%2,%3},{%4,%5,%6,%7},{%8,%9},{%0,%1,%2,%3};"
        : "+f"(c[0]), "+f"(c[1]), "+f"(c[2]), "+f"(c[3])
        : "r"(a[0]), "r"(a[1]), "r"(a[2]), "r"(a[3]), "r"(b[0]), "r"(b[1]));
}
__device__ __forceinline__ float gelu_f(float v) {
    const float c = 0.7978845608028654f;
    float u = c * (v + 0.044715f * v * v * v);
    return 0.5f * v * (1.0f + tanhf(u));
}
// fast exp on the FMA pipe (no MUFU). rel err ~4e-5.
__device__ __forceinline__ float fexp(float x) {
    x = fmaxf(x, -87.0f);
    float z = x * 1.442695041f;
    float t = z + 12582912.0f;
    float n = t - 12582912.0f;
    float r = z - n;
    float p = 9.61812910e-3f;
    p = fmaf(p, r, 5.55041087e-2f);
    p = fmaf(p, r, 2.40226507e-1f);
    p = fmaf(p, r, 6.93147182e-1f);
    p = fmaf(p, r, 1.0f);
    return __int_as_float(__float_as_int(p) + (__float_as_int(t) << 23));
}

// ---------------------------------------------------------------------------
__global__ void zero_ent_kernel(float* e) { *e = 0.0f; }

// one-shot weight conversion: rna tf32 rounding into scratch
__global__ void cvt_tf32_kernel(const float4* __restrict__ in,
                                float4* __restrict__ out, int n4)
{
    int i = blockIdx.x * 256 + threadIdx.x;
    if (i < n4) {
        float4 v = in[i];
        v.x = tf32f(v.x); v.y = tf32f(v.y);
        v.z = tf32f(v.z); v.w = tf32f(v.w);
        out[i] = v;
    }
}

// ---------------------------------------------------------------------------
// LayerNorm: one block per row, 256 threads, 1 float4/thread; output
// tf32-rounded (feeds GEMM A operands only).
__global__ void ln_kernel(const float* __restrict__ x,
                          const float* __restrict__ w,
                          const float* __restrict__ b,
                          float* __restrict__ out)
{
    int row = blockIdx.x, tid = threadIdx.x;
    float4 v = ((const float4*)(x + (long)row * Cc))[tid];
    float s  = v.x + v.y + v.z + v.w;
    float s2 = v.x*v.x + v.y*v.y + v.z*v.z + v.w*v.w;
    __shared__ float rs[8], rs2[8];
    #pragma unroll
    for (int o = 16; o; o >>= 1) {
        s  += __shfl_xor_sync(0xffffffffu, s,  o);
        s2 += __shfl_xor_sync(0xffffffffu, s2, o);
    }
    int lane = tid & 31, wid = tid >> 5;
    if (lane == 0) { rs[wid] = s; rs2[wid] = s2; }
    __syncthreads();
    if (wid == 0) {
        s  = (lane < 8) ? rs[lane]  : 0.f;
        s2 = (lane < 8) ? rs2[lane] : 0.f;
        #pragma unroll
        for (int o = 4; o; o >>= 1) {
            s  += __shfl_xor_sync(0xffffffffu, s,  o);
            s2 += __shfl_xor_sync(0xffffffffu, s2, o);
        }
        if (lane == 0) { rs[0] = s; rs2[0] = s2; }
    }
    __syncthreads();
    float mean = rs[0] * (1.0f / Cc);
    float var  = rs2[0] * (1.0f / Cc) - mean * mean;
    float inv  = rsqrtf(var + 1e-5f);
    float4 w4 = ((const float4*)w)[tid];
    float4 b4 = ((const float4*)b)[tid];
    float4 o4;
    o4.x = tf32f((v.x - mean) * inv * w4.x + b4.x);
    o4.y = tf32f((v.y - mean) * inv * w4.y + b4.y);
    o4.z = tf32f((v.z - mean) * inv * w4.z + b4.z);
    o4.w = tf32f((v.w - mean) * inv * w4.w + b4.w);
    ((float4*)(out + (long)row * Cc))[tid] = o4;
}

// ---------------------------------------------------------------------------
// tf32 mma.sync GEMM with cp.async pipeline.
// C[M,N] = A[M,K] @ W[N,K]^T (+bias, +epilogue). A and W must already be
// tf32-valued fp32. 128x128 CTA tile, BK=32, 4 stages, 8 warps (2m x 4n),
// 64x32 warp tile, m16n8k8.
// EPI: 0 = QKV scatter, 1 = bias+res, 2 = gelu(bias+acc) tf32-rounded
template <int EPI>
__global__ __launch_bounds__(256)
void gemm_cp_kernel(const float* __restrict__ A,
                    const float* __restrict__ W,
                    const float* __restrict__ bias,
                    const float* __restrict__ res,
                    float* __restrict__ outp,
                    float* __restrict__ out_k,
                    float* __restrict__ out_v,
                    float* __restrict__ pres_k,
                    float* __restrict__ pres_v,
                    int K, int N)
{
    extern __shared__ float sf[];
    float* sA = sf;                 // [STG][128][TSg]
    float* sB = sf + STG * ATILE;
    uint32_t sAu = smem_u32(sA), sBu = smem_u32(sB);

    int tid = threadIdx.x;
    int mbase = blockIdx.y * 128, nbase = blockIdx.x * 128;
    int wid = tid >> 5, lane = tid & 31;
    int g = lane >> 2, tig = lane & 3;
    int wm = wid >> 2, wn = wid & 3;
    int moff = wm * 64, noff = wn * 32;
    int nst = K >> 5;

    float acc[4][4][4] = {};

    auto issue = [&](int st) {
        if (st < nst) {
            int k0 = st << 5, buf = st & (STG - 1);
            const float* Ab = A + (long)mbase * K + k0;
            const float* Wb = W + (long)nbase * K + k0;
            #pragma unroll
            for (int i = 0; i < 4; i++) {
                int id = tid + (i << 8);
                int row = id >> 3, c4 = (id & 7) << 2;
                uint32_t off = ((buf * 128 + row) * TSg + c4) * 4;
                cp_async16(sAu + off, Ab + (long)row * K + c4);
                cp_async16(sBu + off, Wb + (long)row * K + c4);
            }
        }
        CP_COMMIT();
    };

    issue(0);
    issue(1);

    for (int it = 0; it < nst; it++) {
        issue(it + 2);
        CP_WAIT2();
        __syncthreads();

        const float* cA = sA + (it & (STG - 1)) * ATILE;
        const float* cB = sB + (it & (STG - 1)) * ATILE;
        #pragma unroll
        for (int x = 0; x < 4; x++) {
            int kk = x * 8;
            unsigned afr[4][4], bfr[4][2];
            #pragma unroll
            for (int mf = 0; mf < 4; mf++) {
                const float* p = cA + (moff + mf * 16 + g) * TSg + kk + tig;
                afr[mf][0] = __float_as_uint(p[0]);
                afr[mf][1] = __float_as_uint(p[8 * TSg]);
                afr[mf][2] = __float_as_uint(p[4]);
                afr[mf][3] = __float_as_uint(p[8 * TSg + 4]);
            }
            #pragma unroll
            for (int nf = 0; nf < 4; nf++) {
                const float* p = cB + (noff + nf * 8 + g) * TSg + kk + tig;
                bfr[nf][0] = __float_as_uint(p[0]);
                bfr[nf][1] = __float_as_uint(p[4]);
            }
            #pragma unroll
            for (int mf = 0; mf < 4; mf++)
                #pragma unroll
                for (int nf = 0; nf < 4; nf++)
                    mma_tf32(acc[mf][nf], afr[mf], bfr[nf]);
        }
        __syncthreads();
    }

    // ---- epilogue (fragment layout identical to R4) ----
    if (EPI == 0) {
        int region = nbase >> 10;
        float* dst  = (region == 0) ? outp : (region == 1) ? out_k  : out_v;
        float* dst2 = (region == 0) ? (float*)0
                    : (region == 1) ? pres_k : pres_v;
        #pragma unroll
        for (int mf = 0; mf < 4; mf++) {
            #pragma unroll
            for (int i = 0; i < 2; i++) {
                int row = mbase + moff + mf * 16 + g + i * 8;
                int bidx = row >> 11;
                int t    = row & (Tc - 1);
                #pragma unroll
                for (int nf = 0; nf < 4; nf++) {
                    #pragma unroll
                    for (int j = 0; j < 2; j++) {
                        int n = nbase + noff + nf * 8 + tig * 2 + j;
                        float v = acc[mf][nf][i * 2 + j] + bias[n];
                        int nl = n & (Cc - 1);
                        int head = nl >> 6, d = nl & 63;
                        long idx = (((long)(bidx * Hc + head) * Tc) + t) * HDc + d;
                        dst[idx] = v;
                        if (dst2) dst2[idx] = v;
                    }
                }
            }
        }
    } else {
        #pragma unroll
        for (int mf = 0; mf < 4; mf++) {
            #pragma unroll
            for (int i = 0; i < 2; i++) {
                int row = mbase + moff + mf * 16 + g + i * 8;
                #pragma unroll
                for (int nf = 0; nf < 4; nf++) {
                    #pragma unroll
                    for (int j = 0; j < 2; j++) {
                        int n = nbase + noff + nf * 8 + tig * 2 + j;
                        float v = acc[mf][nf][i * 2 + j] + bias[n];
                        long idx = (long)row * N + n;
                        if (EPI == 1) v += res[idx];
                        if (EPI == 2) v = tf32f(gelu_f(v));  // feeds MLP GEMM
                        outp[idx] = v;
                    }
                }
            }
        }
    }
}

// ---------------------------------------------------------------------------
// Flash attention on tf32 mma.sync + FMA-pipe exp (R4, Y now tf32-rounded).
__global__ __launch_bounds__(128, 3)
void flash_mma_kernel(const float* __restrict__ Q,
                      const float* __restrict__ Kp,
                      const float* __restrict__ Vp,
                      float* __restrict__ Y,
                      float* __restrict__ ent)
{
    extern __shared__ float sm[];
    float* Qs = sm;
    float* Ks = Qs + 64 * QS_;
    float* Vs = Ks + 64 * KS_;
    float* Ps = Vs + 64 * VS_;
    float* Hs = Ps + 64 * PS_;

    int qt = blockIdx.x, h = blockIdx.y, b = blockIdx.z;
    int tid = threadIdx.x, wid = tid >> 5, lane = tid & 31;
    int g = lane >> 2, tig = lane & 3;
    int wrow = wid * 16;
    long bh = (long)(b * Hc + h);
    const float* Qg = Q  + (bh * Tc + qt * 64) * HDc;
    const float* Kg = Kp + bh * Tc * HDc;
    const float* Vg = Vp + bh * Tc * HDc;

    #pragma unroll
    for (int it = 0; it < 8; it++) {
        int idx = it * 128 + tid;
        int r = idx >> 4, c4 = (idx & 15) << 2;
        float4 v = *(const float4*)(Qg + r * 64 + c4);
        float4 o;
        o.x = tf32f(v.x * 0.125f); o.y = tf32f(v.y * 0.125f);
        o.z = tf32f(v.z * 0.125f); o.w = tf32f(v.w * 0.125f);
        *(float4*)(Qs + r * QS_ + c4) = o;
    }

    float m0 = -1e30f, m1 = -1e30f, l0 = 0.f, l1 = 0.f, ss0 = 0.f, ss1 = 0.f;
    float o_[8][4];
    #pragma unroll
    for (int i = 0; i < 8; i++)
        o_[i][0] = o_[i][1] = o_[i][2] = o_[i][3] = 0.f;

    int row_g0 = qt * 64 + wrow + g;
    int row_g1 = row_g0 + 8;

    for (int kt = 0; kt <= qt; kt++) {
        __syncthreads();
        #pragma unroll
        for (int it = 0; it < 8; it++) {
            int idx = it * 128 + tid;
            int r = idx >> 4, c4 = (idx & 15) << 2;
            float4 kv = *(const float4*)(Kg + (kt * 64 + r) * 64 + c4);
            float4 ko;
            ko.x = tf32f(kv.x); ko.y = tf32f(kv.y);
            ko.z = tf32f(kv.z); ko.w = tf32f(kv.w);
            *(float4*)(Ks + r * KS_ + c4) = ko;
            float4 vv = *(const float4*)(Vg + (kt * 64 + r) * 64 + c4);
            float4 vo;
            vo.x = tf32f(vv.x); vo.y = tf32f(vv.y);
            vo.z = tf32f(vv.z); vo.w = tf32f(vv.w);
            *(float4*)(Vs + r * VS_ + c4) = vo;
        }
        __syncthreads();

        float s[8][4];
        #pragma unroll
        for (int nf = 0; nf < 8; nf++)
            s[nf][0] = s[nf][1] = s[nf][2] = s[nf][3] = 0.f;

        #pragma unroll
        for (int ks = 0; ks < 8; ks++) {
            int kk = ks * 8;
            unsigned a[4];
            const float* qp = Qs + (wrow + g) * QS_ + kk + tig;
            a[0] = __float_as_uint(qp[0]);
            a[1] = __float_as_uint(qp[8 * QS_]);
            a[2] = __float_as_uint(qp[4]);
            a[3] = __float_as_uint(qp[8 * QS_ + 4]);
            #pragma unroll
            for (int nf = 0; nf < 8; nf++) {
                const float* kp2 = Ks + (nf * 8 + g) * KS_ + kk + tig;
                unsigned bb[2] = { __float_as_uint(kp2[0]), __float_as_uint(kp2[4]) };
                mma_tf32(s[nf], a, bb);
            }
        }

        if (kt == qt) {
            #pragma unroll
            for (int nf = 0; nf < 8; nf++) {
                int c = kt * 64 + nf * 8 + 2 * tig;
                if (c     > row_g0) s[nf][0] = -1e30f;
                if (c + 1 > row_g0) s[nf][1] = -1e30f;
                if (c     > row_g1) s[nf][2] = -1e30f;
                if (c + 1 > row_g1) s[nf][3] = -1e30f;
            }
        }

        float rm0 = -1e30f, rm1 = -1e30f;
        #pragma unroll
        for (int nf = 0; nf < 8; nf++) {
            rm0 = fmaxf(rm0, fmaxf(s[nf][0], s[nf][1]));
            rm1 = fmaxf(rm1, fmaxf(s[nf][2], s[nf][3]));
        }
        rm0 = fmaxf(rm0, __shfl_xor_sync(0xffffffffu, rm0, 1));
        rm0 = fmaxf(rm0, __shfl_xor_sync(0xffffffffu, rm0, 2));
        rm1 = fmaxf(rm1, __shfl_xor_sync(0xffffffffu, rm1, 1));
        rm1 = fmaxf(rm1, __shfl_xor_sync(0xffffffffu, rm1, 2));

        float mn0 = fmaxf(m0, rm0), mn1 = fmaxf(m1, rm1);
        float sc0 = fexp(m0 - mn0), sc1 = fexp(m1 - mn1);

        float rs0 = 0.f, rs1 = 0.f, rw0 = 0.f, rw1 = 0.f;
        float* prow0 = Ps + (wrow + g) * PS_ + 2 * tig;
        float* prow1 = prow0 + 8 * PS_;
        #pragma unroll
        for (int nf = 0; nf < 8; nf++) {
            float p00 = fexp(s[nf][0] - mn0), p01 = fexp(s[nf][1] - mn0);
            float p10 = fexp(s[nf][2] - mn1), p11 = fexp(s[nf][3] - mn1);
            rs0 += p00 + p01; rw0 += p00 * s[nf][0] + p01 * s[nf][1];
            rs1 += p10 + p11; rw1 += p10 * s[nf][2] + p11 * s[nf][3];
            *(float2*)(prow0 + nf * 8) = make_float2(tf32f(p00), tf32f(p01));
            *(float2*)(prow1 + nf * 8) = make_float2(tf32f(p10), tf32f(p11));
        }
        #pragma unroll
        for (int o = 1; o <= 2; o <<= 1) {
            rs0 += __shfl_xor_sync(0xffffffffu, rs0, o);
            rw0 += __shfl_xor_sync(0xffffffffu, rw0, o);
            rs1 += __shfl_xor_sync(0xffffffffu, rs1, o);
            rw1 += __shfl_xor_sync(0xffffffffu, rw1, o);
        }
        l0 = l0 * sc0 + rs0;  ss0 = ss0 * sc0 + rw0;  m0 = mn0;
        l1 = l1 * sc1 + rs1;  ss1 = ss1 * sc1 + rw1;  m1 = mn1;

        #pragma unroll
        for (int nf = 0; nf < 8; nf++) {
            o_[nf][0] *= sc0; o_[nf][1] *= sc0;
            o_[nf][2] *= sc1; o_[nf][3] *= sc1;
        }
        __syncwarp();

        #pragma unroll
        for (int ks = 0; ks < 8; ks++) {
            int kk = ks * 8;
            unsigned a[4];
            const float* pp = Ps + (wrow + g) * PS_ + kk + tig;
            a[0] = __float_as_uint(pp[0]);
            a[1] = __float_as_uint(pp[8 * PS_]);
            a[2] = __float_as_uint(pp[4]);
            a[3] = __float_as_uint(pp[8 * PS_ + 4]);
            const float* vbase = Vs + (kk + tig) * VS_ + g;
            #pragma unroll
            for (int nf = 0; nf < 8; nf++) {
                unsigned bb[2] = { __float_as_uint(vbase[nf * 8]),
                                   __float_as_uint(vbase[4 * VS_ + nf * 8]) };
                mma_tf32(o_[nf], a, bb);
            }
        }
    }

    float li0 = 1.f / l0, li1 = 1.f / l1;
    int t0 = qt * 64 + wrow + g;
    float* y0 = Y + ((long)(b * Tc + t0)) * Cc + h * 64 + 2 * tig;
    float* y1 = y0 + 8 * Cc;
    #pragma unroll
    for (int nf = 0; nf < 8; nf++) {
        *(float2*)(y0 + nf * 8) = make_float2(tf32f(o_[nf][0] * li0),
                                              tf32f(o_[nf][1] * li0));
        *(float2*)(y1 + nf * 8) = make_float2(tf32f(o_[nf][2] * li1),
                                              tf32f(o_[nf][3] * li1));
    }

    if (tig == 0) {
        Hs[wrow + g]     = m0 + logf(l0) - ss0 / l0;
        Hs[wrow + g + 8] = m1 + logf(l1) - ss1 / l1;
    }
    __syncthreads();
    if (tid == 0) {
        float sum = 0.f;
        #pragma unroll 8
        for (int i = 0; i < 64; i++) sum += Hs[i];
        atomicAdd(ent, sum * (1.0f / (float)(Bc * Hc * Tc)));
    }
}

// ---------------------------------------------------------------------------
extern "C" void kernel_launch(void* const* d_in, const int* in_sizes, int n_in,
                              void* d_out, int out_size)
{
    const float* x      = (const float*)d_in[0];
    const float* ln1w   = (const float*)d_in[1];
    const float* ln1b   = (const float*)d_in[2];
    const float* w_attn = (const float*)d_in[3];
    const float* b_attn = (const float*)d_in[4];
    const float* w_proj = (const float*)d_in[5];
    const float* b_proj = (const float*)d_in[6];
    const float* ln2w   = (const float*)d_in[7];
    const float* ln2b   = (const float*)d_in[8];
    const float* w_fc   = (const float*)d_in[9];
    const float* b_fc   = (const float*)d_in[10];
    const float* w_mlp  = (const float*)d_in[11];
    const float* b_mlp  = (const float*)d_in[12];

    float* out   = (float*)d_out;
    float* x1    = out;            // x output region
    float* ent   = out + XS;       // scalar entropy
    float* presK = out + XS + 1;   // present[0] (unaligned -- scalar only)
    float* presV = presK + PRES;   // present[1]

    float *ph, *pq, *pk, *pv, *pa, *pwa, *pwp, *pwf, *pwm;
    cudaGetSymbolAddress((void**)&ph,  g_h);
    cudaGetSymbolAddress((void**)&pq,  g_q);
    cudaGetSymbolAddress((void**)&pk,  g_k);
    cudaGetSymbolAddress((void**)&pv,  g_v);
    cudaGetSymbolAddress((void**)&pa,  g_a);
    cudaGetSymbolAddress((void**)&pwa, g_wa);
    cudaGetSymbolAddress((void**)&pwp, g_wp);
    cudaGetSymbolAddress((void**)&pwf, g_wf);
    cudaGetSymbolAddress((void**)&pwm, g_wm);

    cudaFuncSetAttribute(flash_mma_kernel,
                         cudaFuncAttributeMaxDynamicSharedMemorySize, FLASH_SMEM);
    cudaFuncSetAttribute(gemm_cp_kernel<0>,
                         cudaFuncAttributeMaxDynamicSharedMemorySize, GEMM_SMEM);
    cudaFuncSetAttribute(gemm_cp_kernel<1>,
                         cudaFuncAttributeMaxDynamicSharedMemorySize, GEMM_SMEM);
    cudaFuncSetAttribute(gemm_cp_kernel<2>,
                         cudaFuncAttributeMaxDynamicSharedMemorySize, GEMM_SMEM);

    zero_ent_kernel<<<1, 1>>>(ent);

    // one-shot tf32 rounding of the weights into scratch
    {
        int n;
        n = 3 * Cc * Cc / 4;
        cvt_tf32_kernel<<<(n + 255) / 256, 256>>>((const float4*)w_attn, (float4*)pwa, n);
        n = Cc * Cc / 4;
        cvt_tf32_kernel<<<(n + 255) / 256, 256>>>((const float4*)w_proj, (float4*)pwp, n);
        n = 4 * Cc * Cc / 4;
        cvt_tf32_kernel<<<(n + 255) / 256, 256>>>((const float4*)w_fc,   (float4*)pwf, n);
        n = 4 * Cc * Cc / 4;
        cvt_tf32_kernel<<<(n + 255) / 256, 256>>>((const float4*)w_mlp,  (float4*)pwm, n);
    }

    // h = LN1(x)  (tf32-rounded output)
    ln_kernel<<<Mrows, 256>>>(x, ln1w, ln1b, ph);

    // qkv = h @ w_attn^T + b_attn  (q->g_q; k->g_k+present; v->g_v+present)
    {
        dim3 g(3 * Cc / 128, Mrows / 128);
        gemm_cp_kernel<0><<<g, 256, GEMM_SMEM>>>(ph, pwa, b_attn, nullptr,
                                                 pq, pk, pv, presK, presV,
                                                 Cc, 3 * Cc);
    }

    // flash attention: y -> g_h (tf32-rounded), entropy -> ent
    {
        dim3 g(Tc / 64, Hc, Bc);
        flash_mma_kernel<<<g, 128, FLASH_SMEM>>>(pq, pk, pv, ph, ent);
    }

    // x1 = x + y @ w_proj^T + b_proj
    {
        dim3 g(Cc / 128, Mrows / 128);
        gemm_cp_kernel<1><<<g, 256, GEMM_SMEM>>>(ph, pwp, b_proj, x,
                                                 x1, nullptr, nullptr, nullptr, nullptr,
                                                 Cc, Cc);
    }

    // h2 = LN2(x1) -> g_h  (tf32-rounded)
    ln_kernel<<<Mrows, 256>>>(x1, ln2w, ln2b, ph);

    // a = gelu(h2 @ w_fc^T + b_fc) -> g_a  (tf32-rounded in epilogue)
    {
        dim3 g(4 * Cc / 128, Mrows / 128);
        gemm_cp_kernel<2><<<g, 256, GEMM_SMEM>>>(ph, pwf, b_fc, nullptr,
                                                 pa, nullptr, nullptr, nullptr, nullptr,
                                                 Cc, 4 * Cc);
    }

    // x_out = x1 + a @ w_mlp^T + b_mlp
    {
        dim3 g(Cc / 128, Mrows / 128);
        gemm_cp_kernel<1><<<g, 256, GEMM_SMEM>>>(pa, pwm, b_mlp, x1,
                                                 x1, nullptr, nullptr, nullptr, nullptr,
                                                 4 * Cc, Cc);
    }
}

// round 7
// speedup vs baseline: 3.5300x; 1.1163x over previous
#include <cuda_runtime.h>
#include <math.h>
#include <stdint.h>

// ---------------------------------------------------------------------------
// GPT transformer block. GEMMs + flash on tf32 mma.sync (tcgen05 unavailable:
// harness ptxas targets sm_103 without the 'a' feature set).
// GEMM: 128x256 CTA tile, 64x64 warp tile, 3-stage cp.async pipeline.
//   B=2, T=2048, C=1024, H=16, HD=64
// Output layout (float32): [ x (B*T*C) | att_entropy (1) | present (2*B*H*T*HD) ]
// present region starts at float offset XS+1 -> NOT 16B aligned (scalar only).
// ---------------------------------------------------------------------------

namespace {
constexpr int Bc = 2, Tc = 2048, Cc = 1024, Hc = 16, HDc = 64;
constexpr int Mrows = Bc * Tc;            // 4096
constexpr int XS    = Bc * Tc * Cc;       // 4194304
constexpr int PRES  = Bc * Hc * Tc * HDc; // 4194304

// flash smem strides (words) -- conflict-free fragment loads (see R4)
constexpr int QS_ = 68, KS_ = 68, VS_ = 72, PS_ = 68;
constexpr int FLASH_SMEM = (64*QS_ + 64*KS_ + 64*VS_ + 64*PS_ + 64) * 4; // 70912 B

// cp.async GEMM: 128(M) x 256(N) CTA tile, BK=32, 3 pipeline stages
constexpr int TSg   = 36;                  // row stride words (144B, 16B mult)
constexpr int STG   = 3;
constexpr int ATILE = 128 * TSg;           // A words per stage
constexpr int BTILE = 256 * TSg;           // B words per stage
constexpr int GEMM_SMEM = STG * (ATILE + BTILE) * 4; // 165888 B
}

// scratch (device globals -- no allocations allowed)
__device__ float g_h[Mrows * Cc];       // LN outputs / attention y (reused)
__device__ float g_q[PRES];             // Q in (B,H,T,HD)
__device__ float g_k[PRES];             // K in (B,H,T,HD)
__device__ float g_v[PRES];             // V in (B,H,T,HD)
__device__ float g_a[Mrows * 4 * Cc];   // FC activation (B,T,4C)
__device__ float g_wa[3 * Cc * Cc];     // tf32-rounded w_attn
__device__ float g_wp[Cc * Cc];         // tf32-rounded w_proj
__device__ float g_wf[4 * Cc * Cc];     // tf32-rounded w_fc
__device__ float g_wm[4 * Cc * Cc];     // tf32-rounded w_mlp

// ---------------------------------------------------------------------------
__device__ __forceinline__ uint32_t smem_u32(const void* p) {
    uint32_t a;
    asm("{ .reg .u64 t; cvta.to.shared.u64 t, %1; cvt.u32.u64 %0, t; }"
        : "=r"(a) : "l"(p));
    return a;
}
__device__ __forceinline__ void cp_async16(uint32_t dst, const void* src) {
    asm volatile("cp.async.cg.shared.global [%0], [%1], 16;"
                 :: "r"(dst), "l"(src));
}
#define CP_COMMIT() asm volatile("cp.async.commit_group;" ::: "memory")
#define CP_WAIT2()  asm volatile("cp.async.wait_group 2;"  ::: "memory")

__device__ __forceinline__ unsigned f2tf32(float f) {
    unsigned u;
    asm("cvt.rna.tf32.f32 %0, %1;" : "=r"(u) : "f"(f));
    return u;
}
__device__ __forceinline__ float tf32f(float f) {
    return __uint_as_float(f2tf32(f));
}
__device__ __forceinline__ void mma_tf32(float* c, const unsigned* a, const unsigned* b) {
    asm volatile(
        "mma.sync.aligned.m16n8k8.row.col.f32.tf32.tf32.f32 "
        "{%0,%1,%2,%3},{%4,%5,%6,%7},{%8,%9},{%0,%1,%2,%3};"
        : "+f"(c[0]), "+f"(c[1]), "+f"(c[2]), "+f"(c[3])
        : "r"(a[0]), "r"(a[1]), "r"(a[2]), "r"(a[3]), "r"(b[0]), "r"(b[1]));
}
__device__ __forceinline__ float gelu_f(float v) {
    const float c = 0.7978845608028654f;
    float u = c * (v + 0.044715f * v * v * v);
    return 0.5f * v * (1.0f + tanhf(u));
}
// fast exp on the FMA pipe (no MUFU). rel err ~4e-5.
__device__ __forceinline__ float fexp(float x) {
    x = fmaxf(x, -87.0f);
    float z = x * 1.442695041f;
    float t = z + 12582912.0f;
    float n = t - 12582912.0f;
    float r = z - n;
    float p = 9.61812910e-3f;
    p = fmaf(p, r, 5.55041087e-2f);
    p = fmaf(p, r, 2.40226507e-1f);
    p = fmaf(p, r, 6.93147182e-1f);
    p = fmaf(p, r, 1.0f);
    return __int_as_float(__float_as_int(p) + (__float_as_int(t) << 23));
}

// ---------------------------------------------------------------------------
__global__ void zero_ent_kernel(float* e) { *e = 0.0f; }

// one-shot weight conversion: rna tf32 rounding into scratch
__global__ void cvt_tf32_kernel(const float4* __restrict__ in,
                                float4* __restrict__ out, int n4)
{
    int i = blockIdx.x * 256 + threadIdx.x;
    if (i < n4) {
        float4 v = in[i];
        v.x = tf32f(v.x); v.y = tf32f(v.y);
        v.z = tf32f(v.z); v.w = tf32f(v.w);
        out[i] = v;
    }
}

// ---------------------------------------------------------------------------
// LayerNorm: one block per row, 256 threads, 1 float4/thread; tf32 output.
__global__ void ln_kernel(const float* __restrict__ x,
                          const float* __restrict__ w,
                          const float* __restrict__ b,
                          float* __restrict__ out)
{
    int row = blockIdx.x, tid = threadIdx.x;
    float4 v = ((const float4*)(x + (long)row * Cc))[tid];
    float s  = v.x + v.y + v.z + v.w;
    float s2 = v.x*v.x + v.y*v.y + v.z*v.z + v.w*v.w;
    __shared__ float rs[8], rs2[8];
    #pragma unroll
    for (int o = 16; o; o >>= 1) {
        s  += __shfl_xor_sync(0xffffffffu, s,  o);
        s2 += __shfl_xor_sync(0xffffffffu, s2, o);
    }
    int lane = tid & 31, wid = tid >> 5;
    if (lane == 0) { rs[wid] = s; rs2[wid] = s2; }
    __syncthreads();
    if (wid == 0) {
        s  = (lane < 8) ? rs[lane]  : 0.f;
        s2 = (lane < 8) ? rs2[lane] : 0.f;
        #pragma unroll
        for (int o = 4; o; o >>= 1) {
            s  += __shfl_xor_sync(0xffffffffu, s,  o);
            s2 += __shfl_xor_sync(0xffffffffu, s2, o);
        }
        if (lane == 0) { rs[0] = s; rs2[0] = s2; }
    }
    __syncthreads();
    float mean = rs[0] * (1.0f / Cc);
    float var  = rs2[0] * (1.0f / Cc) - mean * mean;
    float inv  = rsqrtf(var + 1e-5f);
    float4 w4 = ((const float4*)w)[tid];
    float4 b4 = ((const float4*)b)[tid];
    float4 o4;
    o4.x = tf32f((v.x - mean) * inv * w4.x + b4.x);
    o4.y = tf32f((v.y - mean) * inv * w4.y + b4.y);
    o4.z = tf32f((v.z - mean) * inv * w4.z + b4.z);
    o4.w = tf32f((v.w - mean) * inv * w4.w + b4.w);
    ((float4*)(out + (long)row * Cc))[tid] = o4;
}

// ---------------------------------------------------------------------------
// tf32 mma.sync GEMM with cp.async pipeline.
// C[M,N] = A[M,K] @ W[N,K]^T (+bias, +epilogue). A, W already tf32-valued.
// CTA tile 128(M)x256(N), BK=32, 3 stages, 8 warps (2m x 4n), 64x64 warp tile.
// EPI: 0 = QKV scatter, 1 = bias+res, 2 = gelu(bias+acc) tf32-rounded
template <int EPI>
__global__ __launch_bounds__(256)
void gemm_cp_kernel(const float* __restrict__ A,
                    const float* __restrict__ W,
                    const float* __restrict__ bias,
                    const float* __restrict__ res,
                    float* __restrict__ outp,
                    float* __restrict__ out_k,
                    float* __restrict__ out_v,
                    float* __restrict__ pres_k,
                    float* __restrict__ pres_v,
                    int K, int N)
{
    extern __shared__ float sf[];
    float* sA = sf;                      // [STG][128][TSg]
    float* sB = sf + STG * ATILE;        // [STG][256][TSg]
    uint32_t sAu = smem_u32(sA), sBu = smem_u32(sB);

    int tid = threadIdx.x;
    int mbase = blockIdx.y * 128, nbase = blockIdx.x * 256;
    int wid = tid >> 5, lane = tid & 31;
    int g = lane >> 2, tig = lane & 3;
    int wm = wid >> 2, wn = wid & 3;     // 2 x 4 warp grid
    int moff = wm * 64, noff = wn * 64;
    int nst = K >> 5;

    float acc[4][8][4] = {};             // 64x64 per warp

    auto issue = [&](int st) {
        if (st < nst) {
            int k0 = st << 5, buf = st % STG;
            const float* Ab = A + (long)mbase * K + k0;
            const float* Wb = W + (long)nbase * K + k0;
            #pragma unroll
            for (int i = 0; i < 4; i++) {        // A: 128 rows
                int id = tid + (i << 8);
                int row = id >> 3, c4 = (id & 7) << 2;
                uint32_t off = ((buf * 128 + row) * TSg + c4) * 4;
                cp_async16(sAu + off, Ab + (long)row * K + c4);
            }
            #pragma unroll
            for (int i = 0; i < 8; i++) {        // B: 256 rows
                int id = tid + (i << 8);
                int row = id >> 3, c4 = (id & 7) << 2;
                uint32_t off = ((buf * 256 + row) * TSg + c4) * 4;
                cp_async16(sBu + off, Wb + (long)row * K + c4);
            }
        }
        CP_COMMIT();
    };

    issue(0);
    issue(1);

    for (int it = 0; it < nst; it++) {
        issue(it + 2);
        CP_WAIT2();
        __syncthreads();

        const float* cA = sA + (it % STG) * ATILE;
        const float* cB = sB + (it % STG) * BTILE;
        #pragma unroll
        for (int x = 0; x < 4; x++) {
            int kk = x * 8;
            unsigned afr[4][4], bfr[8][2];
            #pragma unroll
            for (int mf = 0; mf < 4; mf++) {
                const float* p = cA + (moff + mf * 16 + g) * TSg + kk + tig;
                afr[mf][0] = __float_as_uint(p[0]);
                afr[mf][1] = __float_as_uint(p[8 * TSg]);
                afr[mf][2] = __float_as_uint(p[4]);
                afr[mf][3] = __float_as_uint(p[8 * TSg + 4]);
            }
            #pragma unroll
            for (int nf = 0; nf < 8; nf++) {
                const float* p = cB + (noff + nf * 8 + g) * TSg + kk + tig;
                bfr[nf][0] = __float_as_uint(p[0]);
                bfr[nf][1] = __float_as_uint(p[4]);
            }
            #pragma unroll
            for (int mf = 0; mf < 4; mf++)
                #pragma unroll
                for (int nf = 0; nf < 8; nf++)
                    mma_tf32(acc[mf][nf], afr[mf], bfr[nf]);
        }
        __syncthreads();
    }

    // ---- epilogue ----
    if (EPI == 0) {
        int region = nbase >> 10;            // tile (256 wide) never straddles
        float* dst  = (region == 0) ? outp : (region == 1) ? out_k  : out_v;
        float* dst2 = (region == 0) ? (float*)0
                    : (region == 1) ? pres_k : pres_v;
        #pragma unroll
        for (int mf = 0; mf < 4; mf++) {
            #pragma unroll
            for (int i = 0; i < 2; i++) {
                int row = mbase + moff + mf * 16 + g + i * 8;
                int bidx = row >> 11;
                int t    = row & (Tc - 1);
                #pragma unroll
                for (int nf = 0; nf < 8; nf++) {
                    int n = nbase + noff + nf * 8 + tig * 2;
                    float2 v;
                    v.x = acc[mf][nf][i * 2 + 0] + bias[n];
                    v.y = acc[mf][nf][i * 2 + 1] + bias[n + 1];
                    int nl = n & (Cc - 1);
                    int head = nl >> 6, d = nl & 63;
                    long idx = (((long)(bidx * Hc + head) * Tc) + t) * HDc + d;
                    *(float2*)(dst + idx) = v;
                    if (dst2) { dst2[idx] = v.x; dst2[idx + 1] = v.y; }
                }
            }
        }
    } else {
        #pragma unroll
        for (int mf = 0; mf < 4; mf++) {
            #pragma unroll
            for (int i = 0; i < 2; i++) {
                int row = mbase + moff + mf * 16 + g + i * 8;
                #pragma unroll
                for (int nf = 0; nf < 8; nf++) {
                    int n = nbase + noff + nf * 8 + tig * 2;
                    long idx = (long)row * N + n;
                    float2 v;
                    v.x = acc[mf][nf][i * 2 + 0] + bias[n];
                    v.y = acc[mf][nf][i * 2 + 1] + bias[n + 1];
                    if (EPI == 1) {
                        float2 r2 = *(const float2*)(res + idx);
                        v.x += r2.x; v.y += r2.y;
                    } else {
                        v.x = tf32f(gelu_f(v.x));   // feeds MLP GEMM
                        v.y = tf32f(gelu_f(v.y));
                    }
                    *(float2*)(outp + idx) = v;
                }
            }
        }
    }
}

// ---------------------------------------------------------------------------
// Flash attention on tf32 mma.sync + FMA-pipe exp (unchanged from R6).
__global__ __launch_bounds__(128, 3)
void flash_mma_kernel(const float* __restrict__ Q,
                      const float* __restrict__ Kp,
                      const float* __restrict__ Vp,
                      float* __restrict__ Y,
                      float* __restrict__ ent)
{
    extern __shared__ float sm[];
    float* Qs = sm;
    float* Ks = Qs + 64 * QS_;
    float* Vs = Ks + 64 * KS_;
    float* Ps = Vs + 64 * VS_;
    float* Hs = Ps + 64 * PS_;

    int qt = blockIdx.x, h = blockIdx.y, b = blockIdx.z;
    int tid = threadIdx.x, wid = tid >> 5, lane = tid & 31;
    int g = lane >> 2, tig = lane & 3;
    int wrow = wid * 16;
    long bh = (long)(b * Hc + h);
    const float* Qg = Q  + (bh * Tc + qt * 64) * HDc;
    const float* Kg = Kp + bh * Tc * HDc;
    const float* Vg = Vp + bh * Tc * HDc;

    #pragma unroll
    for (int it = 0; it < 8; it++) {
        int idx = it * 128 + tid;
        int r = idx >> 4, c4 = (idx & 15) << 2;
        float4 v = *(const float4*)(Qg + r * 64 + c4);
        float4 o;
        o.x = tf32f(v.x * 0.125f); o.y = tf32f(v.y * 0.125f);
        o.z = tf32f(v.z * 0.125f); o.w = tf32f(v.w * 0.125f);
        *(float4*)(Qs + r * QS_ + c4) = o;
    }

    float m0 = -1e30f, m1 = -1e30f, l0 = 0.f, l1 = 0.f, ss0 = 0.f, ss1 = 0.f;
    float o_[8][4];
    #pragma unroll
    for (int i = 0; i < 8; i++)
        o_[i][0] = o_[i][1] = o_[i][2] = o_[i][3] = 0.f;

    int row_g0 = qt * 64 + wrow + g;
    int row_g1 = row_g0 + 8;

    for (int kt = 0; kt <= qt; kt++) {
        __syncthreads();
        #pragma unroll
        for (int it = 0; it < 8; it++) {
            int idx = it * 128 + tid;
            int r = idx >> 4, c4 = (idx & 15) << 2;
            float4 kv = *(const float4*)(Kg + (kt * 64 + r) * 64 + c4);
            float4 ko;
            ko.x = tf32f(kv.x); ko.y = tf32f(kv.y);
            ko.z = tf32f(kv.z); ko.w = tf32f(kv.w);
            *(float4*)(Ks + r * KS_ + c4) = ko;
            float4 vv = *(const float4*)(Vg + (kt * 64 + r) * 64 + c4);
            float4 vo;
            vo.x = tf32f(vv.x); vo.y = tf32f(vv.y);
            vo.z = tf32f(vv.z); vo.w = tf32f(vv.w);
            *(float4*)(Vs + r * VS_ + c4) = vo;
        }
        __syncthreads();

        float s[8][4];
        #pragma unroll
        for (int nf = 0; nf < 8; nf++)
            s[nf][0] = s[nf][1] = s[nf][2] = s[nf][3] = 0.f;

        #pragma unroll
        for (int ks = 0; ks < 8; ks++) {
            int kk = ks * 8;
            unsigned a[4];
            const float* qp = Qs + (wrow + g) * QS_ + kk + tig;
            a[0] = __float_as_uint(qp[0]);
            a[1] = __float_as_uint(qp[8 * QS_]);
            a[2] = __float_as_uint(qp[4]);
            a[3] = __float_as_uint(qp[8 * QS_ + 4]);
            #pragma unroll
            for (int nf = 0; nf < 8; nf++) {
                const float* kp2 = Ks + (nf * 8 + g) * KS_ + kk + tig;
                unsigned bb[2] = { __float_as_uint(kp2[0]), __float_as_uint(kp2[4]) };
                mma_tf32(s[nf], a, bb);
            }
        }

        if (kt == qt) {
            #pragma unroll
            for (int nf = 0; nf < 8; nf++) {
                int c = kt * 64 + nf * 8 + 2 * tig;
                if (c     > row_g0) s[nf][0] = -1e30f;
                if (c + 1 > row_g0) s[nf][1] = -1e30f;
                if (c     > row_g1) s[nf][2] = -1e30f;
                if (c + 1 > row_g1) s[nf][3] = -1e30f;
            }
        }

        float rm0 = -1e30f, rm1 = -1e30f;
        #pragma unroll
        for (int nf = 0; nf < 8; nf++) {
            rm0 = fmaxf(rm0, fmaxf(s[nf][0], s[nf][1]));
            rm1 = fmaxf(rm1, fmaxf(s[nf][2], s[nf][3]));
        }
        rm0 = fmaxf(rm0, __shfl_xor_sync(0xffffffffu, rm0, 1));
        rm0 = fmaxf(rm0, __shfl_xor_sync(0xffffffffu, rm0, 2));
        rm1 = fmaxf(rm1, __shfl_xor_sync(0xffffffffu, rm1, 1));
        rm1 = fmaxf(rm1, __shfl_xor_sync(0xffffffffu, rm1, 2));

        float mn0 = fmaxf(m0, rm0), mn1 = fmaxf(m1, rm1);
        float sc0 = fexp(m0 - mn0), sc1 = fexp(m1 - mn1);

        float rs0 = 0.f, rs1 = 0.f, rw0 = 0.f, rw1 = 0.f;
        float* prow0 = Ps + (wrow + g) * PS_ + 2 * tig;
        float* prow1 = prow0 + 8 * PS_;
        #pragma unroll
        for (int nf = 0; nf < 8; nf++) {
            float p00 = fexp(s[nf][0] - mn0), p01 = fexp(s[nf][1] - mn0);
            float p10 = fexp(s[nf][2] - mn1), p11 = fexp(s[nf][3] - mn1);
            rs0 += p00 + p01; rw0 += p00 * s[nf][0] + p01 * s[nf][1];
            rs1 += p10 + p11; rw1 += p10 * s[nf][2] + p11 * s[nf][3];
            *(float2*)(prow0 + nf * 8) = make_float2(tf32f(p00), tf32f(p01));
            *(float2*)(prow1 + nf * 8) = make_float2(tf32f(p10), tf32f(p11));
        }
        #pragma unroll
        for (int o = 1; o <= 2; o <<= 1) {
            rs0 += __shfl_xor_sync(0xffffffffu, rs0, o);
            rw0 += __shfl_xor_sync(0xffffffffu, rw0, o);
            rs1 += __shfl_xor_sync(0xffffffffu, rs1, o);
            rw1 += __shfl_xor_sync(0xffffffffu, rw1, o);
        }
        l0 = l0 * sc0 + rs0;  ss0 = ss0 * sc0 + rw0;  m0 = mn0;
        l1 = l1 * sc1 + rs1;  ss1 = ss1 * sc1 + rw1;  m1 = mn1;

        #pragma unroll
        for (int nf = 0; nf < 8; nf++) {
            o_[nf][0] *= sc0; o_[nf][1] *= sc0;
            o_[nf][2] *= sc1; o_[nf][3] *= sc1;
        }
        __syncwarp();

        #pragma unroll
        for (int ks = 0; ks < 8; ks++) {
            int kk = ks * 8;
            unsigned a[4];
            const float* pp = Ps + (wrow + g) * PS_ + kk + tig;
            a[0] = __float_as_uint(pp[0]);
            a[1] = __float_as_uint(pp[8 * PS_]);
            a[2] = __float_as_uint(pp[4]);
            a[3] = __float_as_uint(pp[8 * PS_ + 4]);
            const float* vbase = Vs + (kk + tig) * VS_ + g;
            #pragma unroll
            for (int nf = 0; nf < 8; nf++) {
                unsigned bb[2] = { __float_as_uint(vbase[nf * 8]),
                                   __float_as_uint(vbase[4 * VS_ + nf * 8]) };
                mma_tf32(o_[nf], a, bb);
            }
        }
    }

    float li0 = 1.f / l0, li1 = 1.f / l1;
    int t0 = qt * 64 + wrow + g;
    float* y0 = Y + ((long)(b * Tc + t0)) * Cc + h * 64 + 2 * tig;
    float* y1 = y0 + 8 * Cc;
    #pragma unroll
    for (int nf = 0; nf < 8; nf++) {
        *(float2*)(y0 + nf * 8) = make_float2(tf32f(o_[nf][0] * li0),
                                              tf32f(o_[nf][1] * li0));
        *(float2*)(y1 + nf * 8) = make_float2(tf32f(o_[nf][2] * li1),
                                              tf32f(o_[nf][3] * li1));
    }

    if (tig == 0) {
        Hs[wrow + g]     = m0 + logf(l0) - ss0 / l0;
        Hs[wrow + g + 8] = m1 + logf(l1) - ss1 / l1;
    }
    __syncthreads();
    if (tid == 0) {
        float sum = 0.f;
        #pragma unroll 8
        for (int i = 0; i < 64; i++) sum += Hs[i];
        atomicAdd(ent, sum * (1.0f / (float)(Bc * Hc * Tc)));
    }
}

// ---------------------------------------------------------------------------
extern "C" void kernel_launch(void* const* d_in, const int* in_sizes, int n_in,
                              void* d_out, int out_size)
{
    const float* x      = (const float*)d_in[0];
    const float* ln1w   = (const float*)d_in[1];
    const float* ln1b   = (const float*)d_in[2];
    const float* w_attn = (const float*)d_in[3];
    const float* b_attn = (const float*)d_in[4];
    const float* w_proj = (const float*)d_in[5];
    const float* b_proj = (const float*)d_in[6];
    const float* ln2w   = (const float*)d_in[7];
    const float* ln2b   = (const float*)d_in[8];
    const float* w_fc   = (const float*)d_in[9];
    const float* b_fc   = (const float*)d_in[10];
    const float* w_mlp  = (const float*)d_in[11];
    const float* b_mlp  = (const float*)d_in[12];

    float* out   = (float*)d_out;
    float* x1    = out;            // x output region
    float* ent   = out + XS;       // scalar entropy
    float* presK = out + XS + 1;   // present[0] (unaligned -- scalar only)
    float* presV = presK + PRES;   // present[1]

    float *ph, *pq, *pk, *pv, *pa, *pwa, *pwp, *pwf, *pwm;
    cudaGetSymbolAddress((void**)&ph,  g_h);
    cudaGetSymbolAddress((void**)&pq,  g_q);
    cudaGetSymbolAddress((void**)&pk,  g_k);
    cudaGetSymbolAddress((void**)&pv,  g_v);
    cudaGetSymbolAddress((void**)&pa,  g_a);
    cudaGetSymbolAddress((void**)&pwa, g_wa);
    cudaGetSymbolAddress((void**)&pwp, g_wp);
    cudaGetSymbolAddress((void**)&pwf, g_wf);
    cudaGetSymbolAddress((void**)&pwm, g_wm);

    cudaFuncSetAttribute(flash_mma_kernel,
                         cudaFuncAttributeMaxDynamicSharedMemorySize, FLASH_SMEM);
    cudaFuncSetAttribute(gemm_cp_kernel<0>,
                         cudaFuncAttributeMaxDynamicSharedMemorySize, GEMM_SMEM);
    cudaFuncSetAttribute(gemm_cp_kernel<1>,
                         cudaFuncAttributeMaxDynamicSharedMemorySize, GEMM_SMEM);
    cudaFuncSetAttribute(gemm_cp_kernel<2>,
                         cudaFuncAttributeMaxDynamicSharedMemorySize, GEMM_SMEM);

    zero_ent_kernel<<<1, 1>>>(ent);

    // one-shot tf32 rounding of the weights into scratch
    {
        int n;
        n = 3 * Cc * Cc / 4;
        cvt_tf32_kernel<<<(n + 255) / 256, 256>>>((const float4*)w_attn, (float4*)pwa, n);
        n = Cc * Cc / 4;
        cvt_tf32_kernel<<<(n + 255) / 256, 256>>>((const float4*)w_proj, (float4*)pwp, n);
        n = 4 * Cc * Cc / 4;
        cvt_tf32_kernel<<<(n + 255) / 256, 256>>>((const float4*)w_fc,   (float4*)pwf, n);
        n = 4 * Cc * Cc / 4;
        cvt_tf32_kernel<<<(n + 255) / 256, 256>>>((const float4*)w_mlp,  (float4*)pwm, n);
    }

    // h = LN1(x)  (tf32-rounded output)
    ln_kernel<<<Mrows, 256>>>(x, ln1w, ln1b, ph);

    // qkv = h @ w_attn^T + b_attn  (q->g_q; k->g_k+present; v->g_v+present)
    {
        dim3 g(3 * Cc / 256, Mrows / 128);
        gemm_cp_kernel<0><<<g, 256, GEMM_SMEM>>>(ph, pwa, b_attn, nullptr,
                                                 pq, pk, pv, presK, presV,
                                                 Cc, 3 * Cc);
    }

    // flash attention: y -> g_h (tf32-rounded), entropy -> ent
    {
        dim3 g(Tc / 64, Hc, Bc);
        flash_mma_kernel<<<g, 128, FLASH_SMEM>>>(pq, pk, pv, ph, ent);
    }

    // x1 = x + y @ w_proj^T + b_proj
    {
        dim3 g(Cc / 256, Mrows / 128);
        gemm_cp_kernel<1><<<g, 256, GEMM_SMEM>>>(ph, pwp, b_proj, x,
                                                 x1, nullptr, nullptr, nullptr, nullptr,
                                                 Cc, Cc);
    }

    // h2 = LN2(x1) -> g_h  (tf32-rounded)
    ln_kernel<<<Mrows, 256>>>(x1, ln2w, ln2b, ph);

    // a = gelu(h2 @ w_fc^T + b_fc) -> g_a  (tf32-rounded in epilogue)
    {
        dim3 g(4 * Cc / 256, Mrows / 128);
        gemm_cp_kernel<2><<<g, 256, GEMM_SMEM>>>(ph, pwf, b_fc, nullptr,
                                                 pa, nullptr, nullptr, nullptr, nullptr,
                                                 Cc, 4 * Cc);
    }

    // x_out = x1 + a @ w_mlp^T + b_mlp
    {
        dim3 g(Cc / 256, Mrows / 128);
        gemm_cp_kernel<1><<<g, 256, GEMM_SMEM>>>(pa, pwm, b_mlp, x1,
                                                 x1, nullptr, nullptr, nullptr, nullptr,
                                                 4 * Cc, Cc);
    }
}